// round 1
// baseline (speedup 1.0000x reference)
#include <cuda_runtime.h>
#include <cstdint>
#include <cmath>

// Problem constants
#define NB   8
#define CC   2048
#define NN   2304      // 48*48
#define MID  512
#define M1   1536      // 3*MID (f,g,h stacked)

// GEMM tiling
#define LDS  136       // 128 + 8 padding (stride mod 32 == 8 -> conflict-free frags)
#define SMEM_BYTES (4 * 32 * 136 * 4)   // 2 bufs * (As+Bs) * 32*136 floats

// ---------------- scratch (device globals; no allocation allowed) ------------
__device__ float g_wfold[(size_t)M1 * CC];          // 12.6 MB
__device__ float g_bfold[M1];
__device__ float g_fgh[(size_t)NB * M1 * NN];       // 113 MB
__device__ float g_z[(size_t)NB * MID * NN];        // 37.7 MB

// ---------------- helpers ----------------------------------------------------
__device__ __forceinline__ uint32_t f2tf(float x) {
    uint32_t u;
    asm("cvt.rna.tf32.f32 %0, %1;" : "=r"(u) : "f"(x));
    return u;
}

__device__ __forceinline__ void mma_tf32(float* c, const uint32_t* a, const uint32_t* b) {
    asm volatile(
        "mma.sync.aligned.m16n8k8.row.col.f32.tf32.tf32.f32 "
        "{%0,%1,%2,%3}, {%4,%5,%6,%7}, {%8,%9}, {%0,%1,%2,%3};\n"
        : "+f"(c[0]), "+f"(c[1]), "+f"(c[2]), "+f"(c[3])
        : "r"(a[0]), "r"(a[1]), "r"(a[2]), "r"(a[3]), "r"(b[0]), "r"(b[1]));
}

// ---------------- BN-fold prep kernel ---------------------------------------
__global__ void fold_kernel(
    const float* __restrict__ f_w, const float* __restrict__ f_b,
    const float* __restrict__ f_g, const float* __restrict__ f_be,
    const float* __restrict__ f_m, const float* __restrict__ f_v,
    const float* __restrict__ g_w, const float* __restrict__ g_b,
    const float* __restrict__ g_g, const float* __restrict__ g_be,
    const float* __restrict__ g_m, const float* __restrict__ g_v,
    const float* __restrict__ h_w, const float* __restrict__ h_b)
{
    int idx = blockIdx.x * 256 + threadIdx.x;
    if (idx >= M1 * CC) return;
    int r = idx / CC, c = idx % CC;
    float w, b;
    if (r < MID) {
        float inv = f_g[r] / sqrtf(f_v[r] + 1e-5f);
        w = f_w[r * CC + c] * inv;
        b = f_b[r] * inv + f_be[r] - f_m[r] * inv;
    } else if (r < 2 * MID) {
        int rr = r - MID;
        float inv = g_g[rr] / sqrtf(g_v[rr] + 1e-5f);
        w = g_w[rr * CC + c] * inv;
        b = g_b[rr] * inv + g_be[rr] - g_m[rr] * inv;
    } else {
        int rr = r - 2 * MID;
        w = h_w[rr * CC + c];
        b = h_b[rr];
    }
    g_wfold[idx] = w;
    if (c == 0) g_bfold[r] = b;
}

// ---------------- generic tiled tf32 GEMM ------------------------------------
// C[m][n] = sum_k A(m,k) * B(k,n)    (all dims multiples of tile sizes)
// ALAY: 0 -> A[m*lda + k] (k contiguous) ; 1 -> A[k*lda + m] (m contiguous)
// BLAY: 0 -> B[k*ldb + n] (n contiguous) ; 1 -> B[n*ldb + k] (k contiguous)
// EPI : 0 none ; 1 +bias[m], relu if m<relu_limit ; 3 +bias[m]+aux[m*ldc+n]
template <int ALAY, int BLAY, int EPI>
__global__ void __launch_bounds__(256, 2)
gemm_tf32(const float* __restrict__ A, long a_bs, int lda,
          const float* __restrict__ B, long b_bs, int ldb,
          float* __restrict__ C, long c_bs, int ldc,
          int K,
          const float* __restrict__ bias, int relu_limit,
          const float* __restrict__ aux, long aux_bs)
{
    extern __shared__ float sm[];
    float* As = sm;                 // [2][32][136]
    float* Bs = sm + 2 * 32 * 136;  // [2][32][136]

    const int tid  = threadIdx.x;
    const int lane = tid & 31;
    const int wid  = tid >> 5;
    const int gid  = lane >> 2;     // 0..7
    const int tg   = lane & 3;      // 0..3
    const int wm   = (wid & 1) * 64;
    const int wn   = (wid >> 1) * 32;
    const long m0  = (long)blockIdx.y * 128;
    const long n0  = (long)blockIdx.x * 128;

    A += (long)blockIdx.z * a_bs;
    B += (long)blockIdx.z * b_bs;
    C += (long)blockIdx.z * c_bs;

    float acc[4][4][4];
#pragma unroll
    for (int i = 0; i < 4; i++)
#pragma unroll
        for (int j = 0; j < 4; j++)
#pragma unroll
            for (int r = 0; r < 4; r++) acc[i][j][r] = 0.0f;

    float4 ra[4], rb[4];
    const int KT = K / 32;

    auto ld_global = [&](int kt) {
        const int kk = kt * 32;
#pragma unroll
        for (int i = 0; i < 4; i++) {
            int idx = tid + i * 256;
            if (ALAY == 0) {
                int m = idx & 127, kq = idx >> 7;
                ra[i] = *reinterpret_cast<const float4*>(A + (m0 + m) * (long)lda + kk + kq * 4);
            } else {
                int k = idx >> 5, mq = idx & 31;
                ra[i] = *reinterpret_cast<const float4*>(A + (long)(kk + k) * lda + m0 + mq * 4);
            }
            if (BLAY == 0) {
                int k = idx >> 5, nq = idx & 31;
                rb[i] = *reinterpret_cast<const float4*>(B + (long)(kk + k) * ldb + n0 + nq * 4);
            } else {
                int n = idx & 127, kq = idx >> 7;
                rb[i] = *reinterpret_cast<const float4*>(B + (n0 + n) * (long)ldb + kk + kq * 4);
            }
        }
    };

    auto st_shared = [&](int buf) {
        float* as = As + buf * (32 * 136);
        float* bs = Bs + buf * (32 * 136);
#pragma unroll
        for (int i = 0; i < 4; i++) {
            int idx = tid + i * 256;
            if (ALAY == 0) {
                int m = idx & 127, kq = idx >> 7;
                as[(kq * 4 + 0) * 136 + m] = __uint_as_float(f2tf(ra[i].x));
                as[(kq * 4 + 1) * 136 + m] = __uint_as_float(f2tf(ra[i].y));
                as[(kq * 4 + 2) * 136 + m] = __uint_as_float(f2tf(ra[i].z));
                as[(kq * 4 + 3) * 136 + m] = __uint_as_float(f2tf(ra[i].w));
            } else {
                int k = idx >> 5, mq = idx & 31;
                float4 v;
                v.x = __uint_as_float(f2tf(ra[i].x));
                v.y = __uint_as_float(f2tf(ra[i].y));
                v.z = __uint_as_float(f2tf(ra[i].z));
                v.w = __uint_as_float(f2tf(ra[i].w));
                *reinterpret_cast<float4*>(as + k * 136 + mq * 4) = v;
            }
            if (BLAY == 0) {
                int k = idx >> 5, nq = idx & 31;
                float4 v;
                v.x = __uint_as_float(f2tf(rb[i].x));
                v.y = __uint_as_float(f2tf(rb[i].y));
                v.z = __uint_as_float(f2tf(rb[i].z));
                v.w = __uint_as_float(f2tf(rb[i].w));
                *reinterpret_cast<float4*>(bs + k * 136 + nq * 4) = v;
            } else {
                int n = idx & 127, kq = idx >> 7;
                bs[(kq * 4 + 0) * 136 + n] = __uint_as_float(f2tf(rb[i].x));
                bs[(kq * 4 + 1) * 136 + n] = __uint_as_float(f2tf(rb[i].y));
                bs[(kq * 4 + 2) * 136 + n] = __uint_as_float(f2tf(rb[i].z));
                bs[(kq * 4 + 3) * 136 + n] = __uint_as_float(f2tf(rb[i].w));
            }
        }
    };

    auto compute = [&](int buf) {
        const float* as = As + buf * (32 * 136);
        const float* bs = Bs + buf * (32 * 136);
#pragma unroll
        for (int ks = 0; ks < 4; ks++) {
            const int kb = ks * 8;
            uint32_t afr[4][4], bfr[4][2];
#pragma unroll
            for (int i = 0; i < 4; i++) {
                const float* p0 = as + (kb + tg) * 136 + wm + i * 16 + gid;
                const float* p1 = as + (kb + tg + 4) * 136 + wm + i * 16 + gid;
                afr[i][0] = __float_as_uint(p0[0]);
                afr[i][1] = __float_as_uint(p0[8]);
                afr[i][2] = __float_as_uint(p1[0]);
                afr[i][3] = __float_as_uint(p1[8]);
            }
#pragma unroll
            for (int j = 0; j < 4; j++) {
                bfr[j][0] = __float_as_uint(bs[(kb + tg) * 136 + wn + j * 8 + gid]);
                bfr[j][1] = __float_as_uint(bs[(kb + tg + 4) * 136 + wn + j * 8 + gid]);
            }
#pragma unroll
            for (int i = 0; i < 4; i++)
#pragma unroll
                for (int j = 0; j < 4; j++)
                    mma_tf32(acc[i][j], afr[i], bfr[j]);
        }
    };

    ld_global(0);
    st_shared(0);
    __syncthreads();
    for (int kt = 0; kt < KT; kt++) {
        int cur = kt & 1;
        if (kt + 1 < KT) ld_global(kt + 1);
        compute(cur);
        if (kt + 1 < KT) {
            st_shared(cur ^ 1);
            __syncthreads();
        }
    }

    // epilogue
#pragma unroll
    for (int i = 0; i < 4; i++) {
        long mr = m0 + wm + i * 16 + gid;
#pragma unroll
        for (int j = 0; j < 4; j++) {
            long nc = n0 + wn + j * 8 + tg * 2;
            float v0 = acc[i][j][0], v1 = acc[i][j][1];
            float v2 = acc[i][j][2], v3 = acc[i][j][3];
            if (EPI == 1) {
                float b0 = bias[mr], b1 = bias[mr + 8];
                v0 += b0; v1 += b0; v2 += b1; v3 += b1;
                if (mr < relu_limit)     { v0 = fmaxf(v0, 0.f); v1 = fmaxf(v1, 0.f); }
                if (mr + 8 < relu_limit) { v2 = fmaxf(v2, 0.f); v3 = fmaxf(v3, 0.f); }
            } else if (EPI == 3) {
                const float* ax = aux + (long)blockIdx.z * aux_bs;
                float b0 = bias[mr], b1 = bias[mr + 8];
                v0 += b0 + ax[mr * ldc + nc];
                v1 += b0 + ax[mr * ldc + nc + 1];
                v2 += b1 + ax[(mr + 8) * ldc + nc];
                v3 += b1 + ax[(mr + 8) * ldc + nc + 1];
            }
            C[mr * ldc + nc]           = v0;
            C[mr * ldc + nc + 1]       = v1;
            C[(mr + 8) * ldc + nc]     = v2;
            C[(mr + 8) * ldc + nc + 1] = v3;
        }
    }
}

// ---------------- row softmax (in place, scale folded in) --------------------
__global__ void __launch_bounds__(256)
softmax_kernel(float* __restrict__ attn, float scale)
{
    float* p = attn + (size_t)blockIdx.x * NN;
    const int t = threadIdx.x;
    float v[9];
    float mx = -1e30f;
#pragma unroll
    for (int i = 0; i < 9; i++) {
        v[i] = p[t + i * 256] * scale;
        mx = fmaxf(mx, v[i]);
    }
    __shared__ float red[8];
#pragma unroll
    for (int o = 16; o > 0; o >>= 1) mx = fmaxf(mx, __shfl_xor_sync(0xffffffffu, mx, o));
    if ((t & 31) == 0) red[t >> 5] = mx;
    __syncthreads();
    if (t == 0) {
        float m = red[0];
#pragma unroll
        for (int i = 1; i < 8; i++) m = fmaxf(m, red[i]);
        red[0] = m;
    }
    __syncthreads();
    mx = red[0];

    float s = 0.f;
#pragma unroll
    for (int i = 0; i < 9; i++) {
        v[i] = expf(v[i] - mx);
        s += v[i];
    }
#pragma unroll
    for (int o = 16; o > 0; o >>= 1) s += __shfl_xor_sync(0xffffffffu, s, o);
    __syncthreads();                       // red reuse barrier
    if ((t & 31) == 0) red[t >> 5] = s;
    __syncthreads();
    if (t == 0) {
        float m = 0.f;
#pragma unroll
        for (int i = 0; i < 8; i++) m += red[i];
        red[0] = m;
    }
    __syncthreads();
    float inv = 1.f / red[0];
#pragma unroll
    for (int i = 0; i < 9; i++) p[t + i * 256] = v[i] * inv;
}

// ---------------- launch ------------------------------------------------------
extern "C" void kernel_launch(void* const* d_in, const int* in_sizes, int n_in,
                              void* d_out, int out_size)
{
    const float* x    = (const float*)d_in[0];
    const float* f_w  = (const float*)d_in[1];
    const float* f_b  = (const float*)d_in[2];
    const float* f_g  = (const float*)d_in[3];
    const float* f_be = (const float*)d_in[4];
    const float* f_m  = (const float*)d_in[5];
    const float* f_v  = (const float*)d_in[6];
    const float* g_w  = (const float*)d_in[7];
    const float* g_b  = (const float*)d_in[8];
    const float* g_g  = (const float*)d_in[9];
    const float* g_be = (const float*)d_in[10];
    const float* g_m  = (const float*)d_in[11];
    const float* g_v  = (const float*)d_in[12];
    const float* h_w  = (const float*)d_in[13];
    const float* h_b  = (const float*)d_in[14];
    const float* v_w  = (const float*)d_in[15];
    const float* v_b  = (const float*)d_in[16];

    float* out  = (float*)d_out;
    float* attn = out + (size_t)NB * CC * NN;   // second tuple element region

    float *wfold, *bfold, *fgh, *z;
    cudaGetSymbolAddress((void**)&wfold, g_wfold);
    cudaGetSymbolAddress((void**)&bfold, g_bfold);
    cudaGetSymbolAddress((void**)&fgh,   g_fgh);
    cudaGetSymbolAddress((void**)&z,     g_z);

    cudaFuncSetAttribute(gemm_tf32<0, 0, 1>, cudaFuncAttributeMaxDynamicSharedMemorySize, SMEM_BYTES);
    cudaFuncSetAttribute(gemm_tf32<1, 0, 0>, cudaFuncAttributeMaxDynamicSharedMemorySize, SMEM_BYTES);
    cudaFuncSetAttribute(gemm_tf32<0, 1, 0>, cudaFuncAttributeMaxDynamicSharedMemorySize, SMEM_BYTES);
    cudaFuncSetAttribute(gemm_tf32<0, 0, 3>, cudaFuncAttributeMaxDynamicSharedMemorySize, SMEM_BYTES);

    // 0) fold BN into conv weights/bias (f,g) + copy h
    fold_kernel<<<(M1 * CC + 255) / 256, 256>>>(
        f_w, f_b, f_g, f_be, f_m, f_v,
        g_w, g_b, g_g, g_be, g_m, g_v,
        h_w, h_b);

    // 1) FGH = Wfold @ X   [1536 x 2304] per batch, bias + relu(first 1024 rows)
    gemm_tf32<0, 0, 1><<<dim3(NN / 128, M1 / 128, NB), 256, SMEM_BYTES>>>(
        wfold, 0L, CC,
        x, (long)CC * NN, NN,
        fgh, (long)M1 * NN, NN,
        CC, bfold, 2 * MID, nullptr, 0L);

    // 2) scores = f^T @ g  [2304 x 2304] per batch  -> attn region (raw logits)
    gemm_tf32<1, 0, 0><<<dim3(NN / 128, NN / 128, NB), 256, SMEM_BYTES>>>(
        fgh, (long)M1 * NN, NN,
        fgh + (size_t)MID * NN, (long)M1 * NN, NN,
        attn, (long)NN * NN, NN,
        MID, nullptr, 0, nullptr, 0L);

    // 3) softmax rows (scale = mid^-0.5 folded in), in place
    softmax_kernel<<<NB * NN, 256>>>(attn, 0.044194173824159223f);

    // 4) z = h @ attn^T    [512 x 2304] per batch
    gemm_tf32<0, 1, 0><<<dim3(NN / 128, MID / 128, NB), 256, SMEM_BYTES>>>(
        fgh + (size_t)2 * MID * NN, (long)M1 * NN, NN,
        attn, (long)NN * NN, NN,
        z, (long)MID * NN, NN,
        NN, nullptr, 0, nullptr, 0L);

    // 5) out = v_w @ z + v_b + x   [2048 x 2304] per batch
    gemm_tf32<0, 0, 3><<<dim3(NN / 128, CC / 128, NB), 256, SMEM_BYTES>>>(
        v_w, 0L, MID,
        z, (long)MID * NN, NN,
        out, (long)CC * NN, NN,
        MID, v_b, 0, x, (long)CC * NN);
}

// round 3
// speedup vs baseline: 1.5487x; 1.5487x over previous
#include <cuda_runtime.h>
#include <cstdint>
#include <cmath>

#define NB   8
#define CC   2048
#define NN   2304
#define MID  512
#define M1   1536

// ---------------- scratch ----------------------------------------------------
__device__ float g_wfold[(size_t)M1 * CC];      // folded+rounded f(scaled),g,h weights
__device__ float g_bfold[M1];
__device__ float g_vwr[(size_t)CC * MID];       // tf32-rounded v_w
__device__ float g_fgh[(size_t)NB * M1 * NN];   // f|g|h activations [b, r, n]
__device__ float g_z[(size_t)NB * MID * NN];    // z [b, c, n]

// ---------------- helpers ------------------------------------------------------
__device__ __forceinline__ float f2tf_rna(float x) {
    uint32_t u;
    asm("cvt.rna.tf32.f32 %0, %1;" : "=r"(u) : "f"(x));
    return __uint_as_float(u);
}
__device__ __forceinline__ uint32_t smem_u32(const void* p) {
    uint32_t a;
    asm("{ .reg .u64 t; cvta.to.shared.u64 t, %1; cvt.u32.u64 %0, t; }" : "=r"(a) : "l"(p));
    return a;
}
__device__ __forceinline__ void mma_tf32(float* c, const uint32_t* a, const uint32_t* b) {
    asm volatile(
        "mma.sync.aligned.m16n8k8.row.col.f32.tf32.tf32.f32 "
        "{%0,%1,%2,%3}, {%4,%5,%6,%7}, {%8,%9}, {%0,%1,%2,%3};\n"
        : "+f"(c[0]), "+f"(c[1]), "+f"(c[2]), "+f"(c[3])
        : "r"(a[0]), "r"(a[1]), "r"(a[2]), "r"(a[3]), "r"(b[0]), "r"(b[1]));
}
__device__ __forceinline__ void cp16(uint32_t saddr, const void* gaddr) {
    asm volatile("cp.async.cg.shared.global [%0], [%1], 16;" :: "r"(saddr), "l"(gaddr) : "memory");
}

// ---------------- BN fold + weight rounding ------------------------------------
__global__ void fold_kernel(
    const float* __restrict__ f_w, const float* __restrict__ f_b,
    const float* __restrict__ f_g, const float* __restrict__ f_be,
    const float* __restrict__ f_m, const float* __restrict__ f_v,
    const float* __restrict__ g_w, const float* __restrict__ g_b,
    const float* __restrict__ g_g, const float* __restrict__ g_be,
    const float* __restrict__ g_m, const float* __restrict__ g_v,
    const float* __restrict__ h_w, const float* __restrict__ h_b,
    const float* __restrict__ v_w)
{
    const float SC = 0.044194173824159223f;  // mid^-0.5 folded into f
    int idx = blockIdx.x * 256 + threadIdx.x;
    int total = M1 * CC + CC * MID;
    if (idx >= total) return;
    if (idx >= M1 * CC) {
        int j = idx - M1 * CC;
        g_vwr[j] = f2tf_rna(v_w[j]);
        return;
    }
    int r = idx / CC, c = idx % CC;
    float w, b;
    if (r < MID) {
        float inv = f_g[r] / sqrtf(f_v[r] + 1e-5f);
        w = f_w[r * CC + c] * inv * SC;
        b = (f_b[r] * inv + f_be[r] - f_m[r] * inv) * SC;
    } else if (r < 2 * MID) {
        int rr = r - MID;
        float inv = g_g[rr] / sqrtf(g_v[rr] + 1e-5f);
        w = g_w[rr * CC + c] * inv;
        b = g_b[rr] * inv + g_be[rr] - g_m[rr] * inv;
    } else {
        int rr = r - 2 * MID;
        w = h_w[rr * CC + c];
        b = h_b[rr];
    }
    g_wfold[idx] = f2tf_rna(w);
    if (c == 0) g_bfold[r] = b;
}

// ---------------- tiled tf32 GEMM, cp.async pipeline ----------------------------
// C[m][n] = sum_k A(m,k) * B(k,n).
// ALAY: 0 -> A[m*lda+k] (k contig) ; 1 -> A[k*lda+m] (m contig)
// BLAY: 0 -> B[k*ldb+n] (n contig) ; 1 -> B[n*ldb+k] (k contig)
// EPI : 0 none ; 1 +bias[m], relu if m<relu_limit ; 3 +bias[m]+aux
// ROUND: tf32-round outputs.  CVTB: tf32-round B fragments in-loop.
constexpr int ST = 5;
constexpr int A_FLT = 4608;     // max A tile floats: 128*36 or 32*136(+pad)
constexpr int STAGE_FLT = 9216; // A + B regions
constexpr int GEMM_SMEM = ST * STAGE_FLT * 4;   // 184320 B

template <int ALAY, int BLAY, int EPI, int ROUND, int CVTB>
__global__ void __launch_bounds__(256, 1)
gemm_cp(const float* __restrict__ A, long a_bs, int lda,
        const float* __restrict__ B, long b_bs, int ldb,
        float* __restrict__ C, long c_bs, int ldc,
        int K,
        const float* __restrict__ bias, int relu_limit,
        const float* __restrict__ aux, long aux_bs)
{
    extern __shared__ float sm[];
    const uint32_t sm_base = smem_u32(sm);

    const int tid  = threadIdx.x;
    const int lane = tid & 31;
    const int wid  = tid >> 5;
    const int gid  = lane >> 2;
    const int tg   = lane & 3;
    const int wm   = (wid & 1) * 64;
    const int wn   = (wid >> 1) * 32;
    const long m0  = (long)blockIdx.y * 128;
    const long n0  = (long)blockIdx.x * 128;

    A += (long)blockIdx.z * a_bs;
    B += (long)blockIdx.z * b_bs;
    C += (long)blockIdx.z * c_bs;

    float acc[4][4][4];
#pragma unroll
    for (int i = 0; i < 4; i++)
#pragma unroll
        for (int j = 0; j < 4; j++)
#pragma unroll
            for (int r = 0; r < 4; r++) acc[i][j][r] = 0.0f;

    const int KT = K / 32;

    auto load_stage = [&](int s, int kt) {
        const long kk = (long)kt * 32;
        const uint32_t sa = sm_base + (s * STAGE_FLT) * 4;
        const uint32_t sb = sa + A_FLT * 4;
#pragma unroll
        for (int i = 0; i < 4; i++) {
            int idx = tid + i * 256;
            if (ALAY == 0) {                       // A[m][k] -> smem [m][36]
                int r = idx >> 3, c = idx & 7;
                cp16(sa + r * 144 + c * 16, A + (m0 + r) * (long)lda + kk + c * 4);
            } else {                               // A[k][m] -> smem [k][136]
                int r = idx >> 5, c = idx & 31;
                cp16(sa + r * 544 + c * 16, A + (kk + r) * (long)lda + m0 + c * 4);
            }
        }
#pragma unroll
        for (int i = 0; i < 4; i++) {
            int idx = tid + i * 256;
            if (BLAY == 0) {                       // B[k][n] -> smem [k][136]
                int r = idx >> 5, c = idx & 31;
                cp16(sb + r * 544 + c * 16, B + (kk + r) * (long)ldb + n0 + c * 4);
            } else {                               // B[n][k] -> smem [n][36]
                int r = idx >> 3, c = idx & 7;
                cp16(sb + r * 144 + c * 16, B + (n0 + r) * (long)ldb + kk + c * 4);
            }
        }
    };

#pragma unroll
    for (int kt = 0; kt < ST - 1; kt++) {
        if (kt < KT) load_stage(kt, kt);
        asm volatile("cp.async.commit_group;" ::: "memory");
    }

    for (int kt = 0; kt < KT; kt++) {
        const int s = kt % ST;
        asm volatile("cp.async.wait_group %0;" :: "n"(ST - 2) : "memory");
        __syncthreads();

        // prefetch next stage (overwrites stage consumed at kt-1; barrier above protects)
        const int ktl = kt + ST - 1;
        if (ktl < KT) load_stage(ktl % ST, ktl);
        asm volatile("cp.async.commit_group;" ::: "memory");

        const float* as = sm + s * STAGE_FLT;
        const float* bs = as + A_FLT;
#pragma unroll
        for (int ks = 0; ks < 4; ks++) {
            const int kb = ks * 8;
            uint32_t afr[4][4], bfr[4][2];
#pragma unroll
            for (int i = 0; i < 4; i++) {
                if (ALAY == 0) {
                    const float* p = as + (wm + i * 16 + gid) * 36 + kb + tg;
                    afr[i][0] = __float_as_uint(p[0]);
                    afr[i][1] = __float_as_uint(p[8 * 36]);
                    afr[i][2] = __float_as_uint(p[4]);
                    afr[i][3] = __float_as_uint(p[8 * 36 + 4]);
                } else {
                    const float* p = as + (kb + tg) * 136 + wm + i * 16 + gid;
                    afr[i][0] = __float_as_uint(p[0]);
                    afr[i][1] = __float_as_uint(p[8]);
                    afr[i][2] = __float_as_uint(p[4 * 136]);
                    afr[i][3] = __float_as_uint(p[4 * 136 + 8]);
                }
            }
#pragma unroll
            for (int j = 0; j < 4; j++) {
                float b0, b1;
                if (BLAY == 0) {
                    const float* p = bs + (kb + tg) * 136 + wn + j * 8 + gid;
                    b0 = p[0]; b1 = p[4 * 136];
                } else {
                    const float* p = bs + (wn + j * 8 + gid) * 36 + kb + tg;
                    b0 = p[0]; b1 = p[4];
                }
                if (CVTB) { b0 = f2tf_rna(b0); b1 = f2tf_rna(b1); }
                bfr[j][0] = __float_as_uint(b0);
                bfr[j][1] = __float_as_uint(b1);
            }
#pragma unroll
            for (int i = 0; i < 4; i++)
#pragma unroll
                for (int j = 0; j < 4; j++)
                    mma_tf32(acc[i][j], afr[i], bfr[j]);
        }
    }

    // ---------------- epilogue ----------------
#pragma unroll
    for (int i = 0; i < 4; i++) {
        long mr = m0 + wm + i * 16 + gid;
#pragma unroll
        for (int j = 0; j < 4; j++) {
            long nc = n0 + wn + j * 8 + tg * 2;
            float v0 = acc[i][j][0], v1 = acc[i][j][1];
            float v2 = acc[i][j][2], v3 = acc[i][j][3];
            if (EPI == 1) {
                float b0 = bias[mr], b1 = bias[mr + 8];
                v0 += b0; v1 += b0; v2 += b1; v3 += b1;
                if (mr < relu_limit)     { v0 = fmaxf(v0, 0.f); v1 = fmaxf(v1, 0.f); }
                if (mr + 8 < relu_limit) { v2 = fmaxf(v2, 0.f); v3 = fmaxf(v3, 0.f); }
            } else if (EPI == 3) {
                const float* ax = aux + (long)blockIdx.z * aux_bs;
                float b0 = bias[mr], b1 = bias[mr + 8];
                const float2 r0 = *reinterpret_cast<const float2*>(ax + mr * ldc + nc);
                const float2 r1 = *reinterpret_cast<const float2*>(ax + (mr + 8) * ldc + nc);
                v0 += b0 + r0.x; v1 += b0 + r0.y;
                v2 += b1 + r1.x; v3 += b1 + r1.y;
            }
            if (ROUND) {
                v0 = f2tf_rna(v0); v1 = f2tf_rna(v1);
                v2 = f2tf_rna(v2); v3 = f2tf_rna(v3);
            }
            float2 s0; s0.x = v0; s0.y = v1;
            float2 s1; s1.x = v2; s1.y = v3;
            *reinterpret_cast<float2*>(C + mr * (long)ldc + nc)       = s0;
            *reinterpret_cast<float2*>(C + (mr + 8) * (long)ldc + nc) = s1;
        }
    }
}

// ---------------- row softmax (in place, rounded output) -----------------------
__global__ void __launch_bounds__(256)
softmax_kernel(float* __restrict__ attn)
{
    float* p = attn + (size_t)blockIdx.x * NN;
    const int t = threadIdx.x;
    float v[9];
    float mx = -1e30f;
#pragma unroll
    for (int i = 0; i < 9; i++) {
        v[i] = p[t + i * 256];
        mx = fmaxf(mx, v[i]);
    }
    __shared__ float red[8];
#pragma unroll
    for (int o = 16; o > 0; o >>= 1) mx = fmaxf(mx, __shfl_xor_sync(0xffffffffu, mx, o));
    if ((t & 31) == 0) red[t >> 5] = mx;
    __syncthreads();
    if (t == 0) {
        float m = red[0];
#pragma unroll
        for (int i = 1; i < 8; i++) m = fmaxf(m, red[i]);
        red[0] = m;
    }
    __syncthreads();
    mx = red[0];

    float s = 0.f;
#pragma unroll
    for (int i = 0; i < 9; i++) {
        v[i] = expf(v[i] - mx);
        s += v[i];
    }
#pragma unroll
    for (int o = 16; o > 0; o >>= 1) s += __shfl_xor_sync(0xffffffffu, s, o);
    __syncthreads();
    if ((t & 31) == 0) red[t >> 5] = s;
    __syncthreads();
    if (t == 0) {
        float m = 0.f;
#pragma unroll
        for (int i = 0; i < 8; i++) m += red[i];
        red[0] = m;
    }
    __syncthreads();
    float inv = 1.f / red[0];
#pragma unroll
    for (int i = 0; i < 9; i++) p[t + i * 256] = f2tf_rna(v[i] * inv);
}

// ---------------- launch ---------------------------------------------------------
extern "C" void kernel_launch(void* const* d_in, const int* in_sizes, int n_in,
                              void* d_out, int out_size)
{
    const float* x    = (const float*)d_in[0];
    const float* f_w  = (const float*)d_in[1];
    const float* f_b  = (const float*)d_in[2];
    const float* f_g  = (const float*)d_in[3];
    const float* f_be = (const float*)d_in[4];
    const float* f_m  = (const float*)d_in[5];
    const float* f_v  = (const float*)d_in[6];
    const float* g_w  = (const float*)d_in[7];
    const float* g_b  = (const float*)d_in[8];
    const float* g_g  = (const float*)d_in[9];
    const float* g_be = (const float*)d_in[10];
    const float* g_m  = (const float*)d_in[11];
    const float* g_v  = (const float*)d_in[12];
    const float* h_w  = (const float*)d_in[13];
    const float* h_b  = (const float*)d_in[14];
    const float* v_w  = (const float*)d_in[15];
    const float* v_b  = (const float*)d_in[16];

    float* out  = (float*)d_out;
    float* attn = out + (size_t)NB * CC * NN;

    float *wfold, *bfold, *vwr, *fgh, *z;
    cudaGetSymbolAddress((void**)&wfold, g_wfold);
    cudaGetSymbolAddress((void**)&bfold, g_bfold);
    cudaGetSymbolAddress((void**)&vwr,   g_vwr);
    cudaGetSymbolAddress((void**)&fgh,   g_fgh);
    cudaGetSymbolAddress((void**)&z,     g_z);

    cudaFuncSetAttribute(gemm_cp<0, 0, 1, 1, 1>, cudaFuncAttributeMaxDynamicSharedMemorySize, GEMM_SMEM);
    cudaFuncSetAttribute(gemm_cp<1, 0, 0, 0, 0>, cudaFuncAttributeMaxDynamicSharedMemorySize, GEMM_SMEM);
    cudaFuncSetAttribute(gemm_cp<0, 1, 0, 1, 0>, cudaFuncAttributeMaxDynamicSharedMemorySize, GEMM_SMEM);
    cudaFuncSetAttribute(gemm_cp<0, 0, 3, 0, 0>, cudaFuncAttributeMaxDynamicSharedMemorySize, GEMM_SMEM);

    // 0) fold BN into weights (f pre-scaled by mid^-0.5), tf32-round weights
    int fold_total = M1 * CC + CC * MID;
    fold_kernel<<<(fold_total + 255) / 256, 256>>>(
        f_w, f_b, f_g, f_be, f_m, f_v,
        g_w, g_b, g_g, g_be, g_m, g_v,
        h_w, h_b, v_w);

    // 1) FGH = Wfold @ X  (bias + relu rows<1024, rounded output)
    gemm_cp<0, 0, 1, 1, 1><<<dim3(NN / 128, M1 / 128, NB), 256, GEMM_SMEM>>>(
        wfold, 0L, CC,
        x, (long)CC * NN, NN,
        fgh, (long)M1 * NN, NN,
        CC, bfold, 2 * MID, nullptr, 0L);

    // 2) scores = f^T @ g  (scale pre-folded into f)
    gemm_cp<1, 0, 0, 0, 0><<<dim3(NN / 128, NN / 128, NB), 256, GEMM_SMEM>>>(
        fgh, (long)M1 * NN, NN,
        fgh + (size_t)MID * NN, (long)M1 * NN, NN,
        attn, (long)NN * NN, NN,
        MID, nullptr, 0, nullptr, 0L);

    // 3) softmax rows (in place, rounded)
    softmax_kernel<<<NB * NN, 256>>>(attn);

    // 4) z = h @ attn^T  (rounded output)
    gemm_cp<0, 1, 0, 1, 0><<<dim3(NN / 128, MID / 128, NB), 256, GEMM_SMEM>>>(
        fgh + (size_t)2 * MID * NN, (long)M1 * NN, NN,
        attn, (long)NN * NN, NN,
        z, (long)MID * NN, NN,
        NN, nullptr, 0, nullptr, 0L);

    // 5) out = v_w @ z + v_b + x
    gemm_cp<0, 0, 3, 0, 0><<<dim3(NN / 128, CC / 128, NB), 256, GEMM_SMEM>>>(
        vwr, 0L, MID,
        z, (long)MID * NN, NN,
        out, (long)CC * NN, NN,
        MID, v_b, 0, x, (long)CC * NN);
}

// round 4
// speedup vs baseline: 1.7234x; 1.1128x over previous
#include <cuda_runtime.h>
#include <cstdint>
#include <cmath>

#define NB   8
#define CC   2048
#define NN   2304
#define MID  512
#define M1   1536

// ---------------- scratch ----------------------------------------------------
__device__ float g_wfold[(size_t)M1 * CC];      // folded+rounded f(scaled),g,h weights
__device__ float g_bfold[M1];
__device__ float g_vwr[(size_t)CC * MID];       // tf32-rounded v_w
__device__ float g_fgh[(size_t)NB * M1 * NN];   // f|g|h activations [b, r, n]
__device__ float g_z[(size_t)NB * MID * NN];    // z [b, c, n]

// ---------------- helpers ------------------------------------------------------
__device__ __forceinline__ float f2tf_rna(float x) {
    uint32_t u;
    asm("cvt.rna.tf32.f32 %0, %1;" : "=r"(u) : "f"(x));
    return __uint_as_float(u);
}
__device__ __forceinline__ uint32_t smem_u32(const void* p) {
    uint32_t a;
    asm("{ .reg .u64 t; cvta.to.shared.u64 t, %1; cvt.u32.u64 %0, t; }" : "=r"(a) : "l"(p));
    return a;
}
__device__ __forceinline__ void mma_tf32(float* c, const uint32_t* a, const uint32_t* b) {
    asm volatile(
        "mma.sync.aligned.m16n8k8.row.col.f32.tf32.tf32.f32 "
        "{%0,%1,%2,%3}, {%4,%5,%6,%7}, {%8,%9}, {%0,%1,%2,%3};\n"
        : "+f"(c[0]), "+f"(c[1]), "+f"(c[2]), "+f"(c[3])
        : "r"(a[0]), "r"(a[1]), "r"(a[2]), "r"(a[3]), "r"(b[0]), "r"(b[1]));
}
__device__ __forceinline__ void cp16(uint32_t saddr, const void* gaddr) {
    asm volatile("cp.async.cg.shared.global [%0], [%1], 16;" :: "r"(saddr), "l"(gaddr) : "memory");
}

// ---------------- BN fold + weight rounding ------------------------------------
__global__ void fold_kernel(
    const float* __restrict__ f_w, const float* __restrict__ f_b,
    const float* __restrict__ f_g, const float* __restrict__ f_be,
    const float* __restrict__ f_m, const float* __restrict__ f_v,
    const float* __restrict__ g_w, const float* __restrict__ g_b,
    const float* __restrict__ g_g, const float* __restrict__ g_be,
    const float* __restrict__ g_m, const float* __restrict__ g_v,
    const float* __restrict__ h_w, const float* __restrict__ h_b,
    const float* __restrict__ v_w)
{
    const float SC = 0.044194173824159223f;  // mid^-0.5 folded into f
    int idx = blockIdx.x * 256 + threadIdx.x;
    int total = M1 * CC + CC * MID;
    if (idx >= total) return;
    if (idx >= M1 * CC) {
        int j = idx - M1 * CC;
        g_vwr[j] = f2tf_rna(v_w[j]);
        return;
    }
    int r = idx / CC, c = idx % CC;
    float w, b;
    if (r < MID) {
        float inv = f_g[r] / sqrtf(f_v[r] + 1e-5f);
        w = f_w[r * CC + c] * inv * SC;
        b = (f_b[r] * inv + f_be[r] - f_m[r] * inv) * SC;
    } else if (r < 2 * MID) {
        int rr = r - MID;
        float inv = g_g[rr] / sqrtf(g_v[rr] + 1e-5f);
        w = g_w[rr * CC + c] * inv;
        b = g_b[rr] * inv + g_be[rr] - g_m[rr] * inv;
    } else {
        int rr = r - 2 * MID;
        w = h_w[rr * CC + c];
        b = h_b[rr];
    }
    g_wfold[idx] = f2tf_rna(w);
    if (c == 0) g_bfold[r] = b;
}

// ---------------- tiled tf32 GEMM, 128x256 CTA tile, cp.async pipeline ----------
// C[m][n] = sum_k A(m,k) * B(k,n).
// ALAY: 0 -> A[m*lda+k] (k contig) ; 1 -> A[k*lda+m] (m contig)
// BLAY: 0 -> B[k*ldb+n] (n contig) ; 1 -> B[n*ldb+k] (k contig)
// EPI : 0 none ; 1 +bias[m], relu if m<relu_limit ; 3 +bias[m]+aux
// ROUND: tf32-round outputs.  CVTB: tf32-round B fragments in-loop.
constexpr int ST = 4;
constexpr int A_FLT = 4608;      // A tile: 128*36 (ALAY0) or 32*136 (ALAY1)
constexpr int B_FLT = 9216;      // B tile: 32*264 (BLAY0) or 256*36 (BLAY1)
constexpr int STAGE_FLT = A_FLT + B_FLT;        // 13824
constexpr int GEMM_SMEM = ST * STAGE_FLT * 4;   // 221184 B

template <int ALAY, int BLAY, int EPI, int ROUND, int CVTB>
__global__ void __launch_bounds__(256, 1)
gemm_cp(const float* __restrict__ A, long a_bs, int lda,
        const float* __restrict__ B, long b_bs, int ldb,
        float* __restrict__ C, long c_bs, int ldc,
        int K,
        const float* __restrict__ bias, int relu_limit,
        const float* __restrict__ aux, long aux_bs)
{
    extern __shared__ float sm[];
    const uint32_t sm_base = smem_u32(sm);

    const int tid  = threadIdx.x;
    const int lane = tid & 31;
    const int wid  = tid >> 5;
    const int gid  = lane >> 2;
    const int tg   = lane & 3;
    const int wm   = (wid & 1) * 64;      // 2 M-warps
    const int wn   = (wid >> 1) * 64;     // 4 N-warps
    const long m0  = (long)blockIdx.y * 128;
    const long n0  = (long)blockIdx.x * 256;

    A += (long)blockIdx.z * a_bs;
    B += (long)blockIdx.z * b_bs;
    C += (long)blockIdx.z * c_bs;

    float acc[4][8][4];
#pragma unroll
    for (int i = 0; i < 4; i++)
#pragma unroll
        for (int j = 0; j < 8; j++)
#pragma unroll
            for (int r = 0; r < 4; r++) acc[i][j][r] = 0.0f;

    const int KT = K / 32;

    auto load_stage = [&](int s, int kt) {
        const long kk = (long)kt * 32;
        const uint32_t sa = sm_base + (s * STAGE_FLT) * 4;
        const uint32_t sb = sa + A_FLT * 4;
        // A: 128x32 floats -> 1024 cp16
#pragma unroll
        for (int i = 0; i < 4; i++) {
            int idx = tid + i * 256;
            if (ALAY == 0) {                       // A[m][k] -> smem [m][36]
                int r = idx >> 3, c = idx & 7;
                cp16(sa + r * 144 + c * 16, A + (m0 + r) * (long)lda + kk + c * 4);
            } else {                               // A[k][m] -> smem [k][136]
                int r = idx >> 5, c = idx & 31;
                cp16(sa + r * 544 + c * 16, A + (kk + r) * (long)lda + m0 + c * 4);
            }
        }
        // B: 256x32 floats -> 2048 cp16
#pragma unroll
        for (int i = 0; i < 8; i++) {
            int idx = tid + i * 256;
            if (BLAY == 0) {                       // B[k][n] -> smem [k][264]
                int r = idx >> 6, c = idx & 63;
                cp16(sb + r * 1056 + c * 16, B + (kk + r) * (long)ldb + n0 + c * 4);
            } else {                               // B[n][k] -> smem [n][36]
                int r = idx >> 3, c = idx & 7;
                cp16(sb + r * 144 + c * 16, B + (n0 + r) * (long)ldb + kk + c * 4);
            }
        }
    };

#pragma unroll
    for (int kt = 0; kt < ST - 1; kt++) {
        if (kt < KT) load_stage(kt, kt);
        asm volatile("cp.async.commit_group;" ::: "memory");
    }

    for (int kt = 0; kt < KT; kt++) {
        const int s = kt % ST;
        asm volatile("cp.async.wait_group %0;" :: "n"(ST - 2) : "memory");
        __syncthreads();

        // prefetch next stage (overwrites stage consumed at kt-1; barrier protects)
        const int ktl = kt + ST - 1;
        if (ktl < KT) load_stage(ktl % ST, ktl);
        asm volatile("cp.async.commit_group;" ::: "memory");

        const float* as = sm + s * STAGE_FLT;
        const float* bs = as + A_FLT;
#pragma unroll
        for (int ks = 0; ks < 4; ks++) {
            const int kb = ks * 8;
            uint32_t afr[4][4], bfr[8][2];
#pragma unroll
            for (int i = 0; i < 4; i++) {
                if (ALAY == 0) {
                    const float* p = as + (wm + i * 16 + gid) * 36 + kb + tg;
                    afr[i][0] = __float_as_uint(p[0]);
                    afr[i][1] = __float_as_uint(p[8 * 36]);
                    afr[i][2] = __float_as_uint(p[4]);
                    afr[i][3] = __float_as_uint(p[8 * 36 + 4]);
                } else {
                    const float* p = as + (kb + tg) * 136 + wm + i * 16 + gid;
                    afr[i][0] = __float_as_uint(p[0]);
                    afr[i][1] = __float_as_uint(p[8]);
                    afr[i][2] = __float_as_uint(p[4 * 136]);
                    afr[i][3] = __float_as_uint(p[4 * 136 + 8]);
                }
            }
#pragma unroll
            for (int j = 0; j < 8; j++) {
                float b0, b1;
                if (BLAY == 0) {
                    const float* p = bs + (kb + tg) * 264 + wn + j * 8 + gid;
                    b0 = p[0]; b1 = p[4 * 264];
                } else {
                    const float* p = bs + (wn + j * 8 + gid) * 36 + kb + tg;
                    b0 = p[0]; b1 = p[4];
                }
                if (CVTB) { b0 = f2tf_rna(b0); b1 = f2tf_rna(b1); }
                bfr[j][0] = __float_as_uint(b0);
                bfr[j][1] = __float_as_uint(b1);
            }
#pragma unroll
            for (int i = 0; i < 4; i++)
#pragma unroll
                for (int j = 0; j < 8; j++)
                    mma_tf32(acc[i][j], afr[i], bfr[j]);
        }
    }

    // ---------------- epilogue ----------------
#pragma unroll
    for (int i = 0; i < 4; i++) {
        long mr = m0 + wm + i * 16 + gid;
#pragma unroll
        for (int j = 0; j < 8; j++) {
            long nc = n0 + wn + j * 8 + tg * 2;
            float v0 = acc[i][j][0], v1 = acc[i][j][1];
            float v2 = acc[i][j][2], v3 = acc[i][j][3];
            if (EPI == 1) {
                float b0 = bias[mr], b1 = bias[mr + 8];
                v0 += b0; v1 += b0; v2 += b1; v3 += b1;
                if (mr < relu_limit)     { v0 = fmaxf(v0, 0.f); v1 = fmaxf(v1, 0.f); }
                if (mr + 8 < relu_limit) { v2 = fmaxf(v2, 0.f); v3 = fmaxf(v3, 0.f); }
            } else if (EPI == 3) {
                const float* ax = aux + (long)blockIdx.z * aux_bs;
                float b0 = bias[mr], b1 = bias[mr + 8];
                const float2 r0 = *reinterpret_cast<const float2*>(ax + mr * ldc + nc);
                const float2 r1 = *reinterpret_cast<const float2*>(ax + (mr + 8) * ldc + nc);
                v0 += b0 + r0.x; v1 += b0 + r0.y;
                v2 += b1 + r1.x; v3 += b1 + r1.y;
            }
            if (ROUND) {
                v0 = f2tf_rna(v0); v1 = f2tf_rna(v1);
                v2 = f2tf_rna(v2); v3 = f2tf_rna(v3);
            }
            float2 s0; s0.x = v0; s0.y = v1;
            float2 s1; s1.x = v2; s1.y = v3;
            *reinterpret_cast<float2*>(C + mr * (long)ldc + nc)       = s0;
            *reinterpret_cast<float2*>(C + (mr + 8) * (long)ldc + nc) = s1;
        }
    }
}

// ---------------- row softmax (in place, rounded output) -----------------------
__global__ void __launch_bounds__(256)
softmax_kernel(float* __restrict__ attn)
{
    float* p = attn + (size_t)blockIdx.x * NN;
    const int t = threadIdx.x;
    float v[9];
    float mx = -1e30f;
#pragma unroll
    for (int i = 0; i < 9; i++) {
        v[i] = p[t + i * 256];
        mx = fmaxf(mx, v[i]);
    }
    __shared__ float red[8];
#pragma unroll
    for (int o = 16; o > 0; o >>= 1) mx = fmaxf(mx, __shfl_xor_sync(0xffffffffu, mx, o));
    if ((t & 31) == 0) red[t >> 5] = mx;
    __syncthreads();
    if (t == 0) {
        float m = red[0];
#pragma unroll
        for (int i = 1; i < 8; i++) m = fmaxf(m, red[i]);
        red[0] = m;
    }
    __syncthreads();
    mx = red[0];

    float s = 0.f;
#pragma unroll
    for (int i = 0; i < 9; i++) {
        v[i] = expf(v[i] - mx);
        s += v[i];
    }
#pragma unroll
    for (int o = 16; o > 0; o >>= 1) s += __shfl_xor_sync(0xffffffffu, s, o);
    __syncthreads();
    if ((t & 31) == 0) red[t >> 5] = s;
    __syncthreads();
    if (t == 0) {
        float m = 0.f;
#pragma unroll
        for (int i = 0; i < 8; i++) m += red[i];
        red[0] = m;
    }
    __syncthreads();
    float inv = 1.f / red[0];
#pragma unroll
    for (int i = 0; i < 9; i++) p[t + i * 256] = f2tf_rna(v[i] * inv);
}

// ---------------- launch ---------------------------------------------------------
extern "C" void kernel_launch(void* const* d_in, const int* in_sizes, int n_in,
                              void* d_out, int out_size)
{
    const float* x    = (const float*)d_in[0];
    const float* f_w  = (const float*)d_in[1];
    const float* f_b  = (const float*)d_in[2];
    const float* f_g  = (const float*)d_in[3];
    const float* f_be = (const float*)d_in[4];
    const float* f_m  = (const float*)d_in[5];
    const float* f_v  = (const float*)d_in[6];
    const float* g_w  = (const float*)d_in[7];
    const float* g_b  = (const float*)d_in[8];
    const float* g_g  = (const float*)d_in[9];
    const float* g_be = (const float*)d_in[10];
    const float* g_m  = (const float*)d_in[11];
    const float* g_v  = (const float*)d_in[12];
    const float* h_w  = (const float*)d_in[13];
    const float* h_b  = (const float*)d_in[14];
    const float* v_w  = (const float*)d_in[15];
    const float* v_b  = (const float*)d_in[16];

    float* out  = (float*)d_out;
    float* attn = out + (size_t)NB * CC * NN;

    float *wfold, *bfold, *vwr, *fgh, *z;
    cudaGetSymbolAddress((void**)&wfold, g_wfold);
    cudaGetSymbolAddress((void**)&bfold, g_bfold);
    cudaGetSymbolAddress((void**)&vwr,   g_vwr);
    cudaGetSymbolAddress((void**)&fgh,   g_fgh);
    cudaGetSymbolAddress((void**)&z,     g_z);

    cudaFuncSetAttribute(gemm_cp<0, 0, 1, 1, 1>, cudaFuncAttributeMaxDynamicSharedMemorySize, GEMM_SMEM);
    cudaFuncSetAttribute(gemm_cp<1, 0, 0, 0, 0>, cudaFuncAttributeMaxDynamicSharedMemorySize, GEMM_SMEM);
    cudaFuncSetAttribute(gemm_cp<0, 1, 0, 1, 0>, cudaFuncAttributeMaxDynamicSharedMemorySize, GEMM_SMEM);
    cudaFuncSetAttribute(gemm_cp<0, 0, 3, 0, 0>, cudaFuncAttributeMaxDynamicSharedMemorySize, GEMM_SMEM);

    // 0) fold BN into weights (f pre-scaled by mid^-0.5), tf32-round weights
    int fold_total = M1 * CC + CC * MID;
    fold_kernel<<<(fold_total + 255) / 256, 256>>>(
        f_w, f_b, f_g, f_be, f_m, f_v,
        g_w, g_b, g_g, g_be, g_m, g_v,
        h_w, h_b, v_w);

    // 1) FGH = Wfold @ X  (bias + relu rows<1024, rounded output)
    gemm_cp<0, 0, 1, 1, 1><<<dim3(NN / 256, M1 / 128, NB), 256, GEMM_SMEM>>>(
        wfold, 0L, CC,
        x, (long)CC * NN, NN,
        fgh, (long)M1 * NN, NN,
        CC, bfold, 2 * MID, nullptr, 0L);

    // 2) scores = f^T @ g  (scale pre-folded into f)
    gemm_cp<1, 0, 0, 0, 0><<<dim3(NN / 256, NN / 128, NB), 256, GEMM_SMEM>>>(
        fgh, (long)M1 * NN, NN,
        fgh + (size_t)MID * NN, (long)M1 * NN, NN,
        attn, (long)NN * NN, NN,
        MID, nullptr, 0, nullptr, 0L);

    // 3) softmax rows (in place, rounded)
    softmax_kernel<<<NB * NN, 256>>>(attn);

    // 4) z = h @ attn^T  (rounded output)
    gemm_cp<0, 1, 0, 1, 0><<<dim3(NN / 256, MID / 128, NB), 256, GEMM_SMEM>>>(
        fgh + (size_t)2 * MID * NN, (long)M1 * NN, NN,
        attn, (long)NN * NN, NN,
        z, (long)MID * NN, NN,
        NN, nullptr, 0, nullptr, 0L);

    // 5) out = v_w @ z + v_b + x
    gemm_cp<0, 0, 3, 0, 0><<<dim3(NN / 256, CC / 128, NB), 256, GEMM_SMEM>>>(
        vwr, 0L, MID,
        z, (long)MID * NN, NN,
        out, (long)CC * NN, NN,
        MID, v_b, 0, x, (long)CC * NN);
}

// round 6
// speedup vs baseline: 1.8797x; 1.0907x over previous
#include <cuda_runtime.h>
#include <cstdint>
#include <cmath>

#define NB   8
#define CC   2048
#define NN   2304
#define MID  512
#define M1   1536

// ---------------- scratch ----------------------------------------------------
__device__ float g_wpk[(size_t)M1 * CC];        // fragment-packed folded weights (GEMM1 A)
__device__ float g_bfold[M1];
__device__ float g_vpk[(size_t)CC * MID];       // fragment-packed rounded v_w (GEMM5 A)
__device__ float g_xpk[(size_t)NB * NN * CC];   // fragment-packed rounded x (GEMM1 B)
__device__ float g_fgh[(size_t)NB * M1 * NN];   // f|g|h activations [b, r, n]
__device__ float g_z[(size_t)NB * MID * NN];    // z [b, c, n]

// ---------------- helpers ------------------------------------------------------
__device__ __forceinline__ float f2tf_rna(float x) {
    uint32_t u;
    asm("cvt.rna.tf32.f32 %0, %1;" : "=r"(u) : "f"(x));
    return __uint_as_float(u);
}
__device__ __forceinline__ uint32_t smem_u32(const void* p) {
    uint32_t a;
    asm("{ .reg .u64 t; cvta.to.shared.u64 t, %1; cvt.u32.u64 %0, t; }" : "=r"(a) : "l"(p));
    return a;
}
__device__ __forceinline__ void mma_tf32(float* c, const uint32_t* a, const uint32_t* b) {
    asm volatile(
        "mma.sync.aligned.m16n8k8.row.col.f32.tf32.tf32.f32 "
        "{%0,%1,%2,%3}, {%4,%5,%6,%7}, {%8,%9}, {%0,%1,%2,%3};\n"
        : "+f"(c[0]), "+f"(c[1]), "+f"(c[2]), "+f"(c[3])
        : "r"(a[0]), "r"(a[1]), "r"(a[2]), "r"(a[3]), "r"(b[0]), "r"(b[1]));
}
__device__ __forceinline__ void cp16(uint32_t saddr, const void* gaddr) {
    asm volatile("cp.async.cg.shared.global [%0], [%1], 16;" :: "r"(saddr), "l"(gaddr) : "memory");
}

// ---------------- prep: bias fold (small) ---------------------------------------
__global__ void prep_bias(
    const float* __restrict__ f_b, const float* __restrict__ f_g,
    const float* __restrict__ f_be, const float* __restrict__ f_m,
    const float* __restrict__ f_v,
    const float* __restrict__ g_b, const float* __restrict__ g_g,
    const float* __restrict__ g_be, const float* __restrict__ g_m,
    const float* __restrict__ g_v,
    const float* __restrict__ h_b)
{
    const float SC = 0.044194173824159223f;
    int r = blockIdx.x * 256 + threadIdx.x;
    if (r >= M1) return;
    float b;
    if (r < MID) {
        float inv = f_g[r] / sqrtf(f_v[r] + 1e-5f);
        b = (f_b[r] * inv + f_be[r] - f_m[r] * inv) * SC;
    } else if (r < 2 * MID) {
        int rr = r - MID;
        float inv = g_g[rr] / sqrtf(g_v[rr] + 1e-5f);
        b = g_b[rr] * inv + g_be[rr] - g_m[rr] * inv;
    } else {
        b = h_b[r - 2 * MID];
    }
    g_bfold[r] = b;
}

// ---------------- prep: pack folded weights (GEMM1 A) ----------------------------
// Layout: [mblk(12)][kt(64)] slabs of 4096 floats; slab = [ks(4)][mt(8)][lane(32)][4]
// float4 elems: {A[m][k], A[m+8][k], A[m][k+4], A[m+8][k+4]}, m=mblk*128+mt*16+gid, k=kt*32+ks*8+tg
__global__ void packw_kernel(
    const float* __restrict__ f_w, const float* __restrict__ f_g, const float* __restrict__ f_v,
    const float* __restrict__ g_w, const float* __restrict__ g_g, const float* __restrict__ g_v,
    const float* __restrict__ h_w)
{
    const float SC = 0.044194173824159223f;
    int idx = blockIdx.x * 256 + threadIdx.x;       // one float4
    if (idx >= M1 * CC / 4) return;
    int lane = idx & 31;
    int ksmt = (idx >> 5) & 31;
    int kt   = (idx >> 10) & 63;
    int mblk = idx >> 16;
    int ks = ksmt >> 3, mt = ksmt & 7;
    int gid = lane >> 2, tg = lane & 3;
    float4 v;
#pragma unroll
    for (int e = 0; e < 4; e++) {
        int m = mblk * 128 + mt * 16 + gid + (e & 1) * 8;
        int c = kt * 32 + ks * 8 + tg + (e >> 1) * 4;
        float w;
        if (m < MID) {
            float inv = f_g[m] / sqrtf(f_v[m] + 1e-5f);
            w = f_w[m * CC + c] * inv * SC;
        } else if (m < 2 * MID) {
            int rr = m - MID;
            float inv = g_g[rr] / sqrtf(g_v[rr] + 1e-5f);
            w = g_w[rr * CC + c] * inv;
        } else {
            w = h_w[(m - 2 * MID) * CC + c];
        }
        (&v.x)[e] = f2tf_rna(w);
    }
    reinterpret_cast<float4*>(g_wpk)[idx] = v;
}

// ---------------- prep: pack v_w (GEMM5 A) ---------------------------------------
// [mblk(16)][kt(16)] slabs of 4096 floats, same slab layout as packw.
__global__ void packv_kernel(const float* __restrict__ v_w)
{
    int idx = blockIdx.x * 256 + threadIdx.x;
    if (idx >= CC * MID / 4) return;
    int lane = idx & 31;
    int ksmt = (idx >> 5) & 31;
    int kt   = (idx >> 10) & 15;
    int mblk = idx >> 14;
    int ks = ksmt >> 3, mt = ksmt & 7;
    int gid = lane >> 2, tg = lane & 3;
    float4 v;
#pragma unroll
    for (int e = 0; e < 4; e++) {
        int m = mblk * 128 + mt * 16 + gid + (e & 1) * 8;
        int c = kt * 32 + ks * 8 + tg + (e >> 1) * 4;
        (&v.x)[e] = f2tf_rna(v_w[m * MID + c]);
    }
    reinterpret_cast<float4*>(g_vpk)[idx] = v;
}

// ---------------- prep: pack + round x (GEMM1 B) ----------------------------------
// Layout: [b][nblk(9)][kt(64)] slabs of 8192 floats; slab = [ks(4)][ntp(16)][lane(32)][4]
// elems: {B[k][na], B[k+4][na], B[k][nb], B[k+4][nb]}, k=kt*32+ks*8+tg,
//        na=(ntp*2)*8+gid+nblk*256, nb=na+8
__global__ void packx_kernel(const float* __restrict__ x)
{
    int idx = blockIdx.x * 256 + threadIdx.x;       // one float4
    // total = NB*9*64*4*16*32 = 9437184 (exactly divisible by 256)
    int lane = idx & 31;
    int ntp  = (idx >> 5) & 15;
    int ks   = (idx >> 9) & 3;
    int kt   = (idx >> 11) & 63;
    int t    = idx >> 17;                            // 0..71
    int nblk = t % 9;
    int b    = t / 9;
    int gid = lane >> 2, tg = lane & 3;
    const float* xb = x + (size_t)b * CC * NN;
    float4 v;
#pragma unroll
    for (int e = 0; e < 4; e++) {
        int c = kt * 32 + ks * 8 + tg + (e & 1) * 4;
        int n = nblk * 256 + (ntp * 2 + (e >> 1)) * 8 + gid;
        (&v.x)[e] = f2tf_rna(xb[(size_t)c * NN + n]);
    }
    reinterpret_cast<float4*>(g_xpk)[idx] = v;
}

// ---------------- tiled tf32 GEMM, 128x256 CTA tile --------------------------------
// C[m][n] = sum_k A(m,k) * B(k,n).
// APACK: A fragment-packed ([mblk][kt] 4096-float slabs).  Else ALAY as before.
// BPACK: B fragment-packed ([nblk][kt] 8192-float slabs).  Else BLAY as before.
// EPI : 0 none ; 1 +bias[m], relu if m<relu_limit ; 3 +bias[m]+aux
constexpr int ST = 4;
constexpr int A_FLT = 4608;
constexpr int B_FLT = 9216;
constexpr int STAGE_FLT = A_FLT + B_FLT;        // 13824
constexpr int GEMM_SMEM = ST * STAGE_FLT * 4;   // 221184 B

template <int APACK, int ALAY, int BPACK, int BLAY, int EPI, int ROUND>
__global__ void __launch_bounds__(256, 1)
gemm_cp(const float* __restrict__ A, long a_bs, int lda,
        const float* __restrict__ B, long b_bs, int ldb,
        float* __restrict__ C, long c_bs, int ldc,
        int K,
        const float* __restrict__ bias, int relu_limit,
        const float* __restrict__ aux, long aux_bs)
{
    extern __shared__ float sm[];
    const uint32_t sm_base = smem_u32(sm);

    const int tid  = threadIdx.x;
    const int lane = tid & 31;
    const int wid  = tid >> 5;
    const int gid  = lane >> 2;
    const int tg   = lane & 3;
    const int wm   = (wid & 1) * 64;      // 2 M-warps
    const int wn   = (wid >> 1) * 64;     // 4 N-warps
    const long m0  = (long)blockIdx.y * 128;
    const long n0  = (long)blockIdx.x * 256;

    A += (long)blockIdx.z * a_bs;
    B += (long)blockIdx.z * b_bs;
    C += (long)blockIdx.z * c_bs;

    const int KT = K / 32;

    float acc[4][8][4];
#pragma unroll
    for (int i = 0; i < 4; i++)
#pragma unroll
        for (int j = 0; j < 8; j++)
#pragma unroll
            for (int r = 0; r < 4; r++) acc[i][j][r] = 0.0f;

    auto load_stage = [&](int s, int kt) {
        const long kk = (long)kt * 32;
        const uint32_t sa = sm_base + (s * STAGE_FLT) * 4;
        const uint32_t sb = sa + A_FLT * 4;
        if (APACK) {                               // linear 16KB slab
            const float* ga = A + ((long)blockIdx.y * KT + kt) * 4096;
#pragma unroll
            for (int i = 0; i < 4; i++) {
                int idx = tid + i * 256;
                cp16(sa + idx * 16, ga + idx * 4);
            }
        } else {
#pragma unroll
            for (int i = 0; i < 4; i++) {
                int idx = tid + i * 256;
                if (ALAY == 0) {                   // A[m][k] -> smem [m][36]
                    int r = idx >> 3, c = idx & 7;
                    cp16(sa + r * 144 + c * 16, A + (m0 + r) * (long)lda + kk + c * 4);
                } else {                           // A[k][m] -> smem [k][136]
                    int r = idx >> 5, c = idx & 31;
                    cp16(sa + r * 544 + c * 16, A + (kk + r) * (long)lda + m0 + c * 4);
                }
            }
        }
        if (BPACK) {                               // linear 32KB slab
            const float* gb = B + ((long)blockIdx.x * KT + kt) * 8192;
#pragma unroll
            for (int i = 0; i < 8; i++) {
                int idx = tid + i * 256;
                cp16(sb + idx * 16, gb + idx * 4);
            }
        } else {
#pragma unroll
            for (int i = 0; i < 8; i++) {
                int idx = tid + i * 256;
                if (BLAY == 0) {                   // B[k][n] -> smem [k][264]
                    int r = idx >> 6, c = idx & 63;
                    cp16(sb + r * 1056 + c * 16, B + (kk + r) * (long)ldb + n0 + c * 4);
                } else {                           // B[n][k] -> smem [n][36]
                    int r = idx >> 3, c = idx & 7;
                    cp16(sb + r * 144 + c * 16, B + (n0 + r) * (long)ldb + kk + c * 4);
                }
            }
        }
    };

#pragma unroll
    for (int kt = 0; kt < ST - 1; kt++) {
        if (kt < KT) load_stage(kt, kt);
        asm volatile("cp.async.commit_group;" ::: "memory");
    }

    for (int kt = 0; kt < KT; kt++) {
        const int s = kt % ST;
        asm volatile("cp.async.wait_group %0;" :: "n"(ST - 2) : "memory");
        __syncthreads();

        const int ktl = kt + ST - 1;
        if (ktl < KT) load_stage(ktl % ST, ktl);
        asm volatile("cp.async.commit_group;" ::: "memory");

        const float* as = sm + s * STAGE_FLT;
        const float* bs = as + A_FLT;
#pragma unroll
        for (int ks = 0; ks < 4; ks++) {
            const int kb = ks * 8;
            uint32_t afr[4][4], bfr[8][2];
            if (APACK) {
#pragma unroll
                for (int i = 0; i < 4; i++) {
                    const float4 av = reinterpret_cast<const float4*>(as)
                        [(ks * 8 + (wid & 1) * 4 + i) * 32 + lane];
                    afr[i][0] = __float_as_uint(av.x);
                    afr[i][1] = __float_as_uint(av.y);
                    afr[i][2] = __float_as_uint(av.z);
                    afr[i][3] = __float_as_uint(av.w);
                }
            } else {
#pragma unroll
                for (int i = 0; i < 4; i++) {
                    if (ALAY == 0) {
                        const float* p = as + (wm + i * 16 + gid) * 36 + kb + tg;
                        afr[i][0] = __float_as_uint(p[0]);
                        afr[i][1] = __float_as_uint(p[8 * 36]);
                        afr[i][2] = __float_as_uint(p[4]);
                        afr[i][3] = __float_as_uint(p[8 * 36 + 4]);
                    } else {
                        const float* p = as + (kb + tg) * 136 + wm + i * 16 + gid;
                        afr[i][0] = __float_as_uint(p[0]);
                        afr[i][1] = __float_as_uint(p[8]);
                        afr[i][2] = __float_as_uint(p[4 * 136]);
                        afr[i][3] = __float_as_uint(p[4 * 136 + 8]);
                    }
                }
            }
            if (BPACK) {
#pragma unroll
                for (int p = 0; p < 4; p++) {
                    const float4 bv = reinterpret_cast<const float4*>(bs)
                        [(ks * 16 + (wid >> 1) * 4 + p) * 32 + lane];
                    bfr[2 * p][0]     = __float_as_uint(bv.x);
                    bfr[2 * p][1]     = __float_as_uint(bv.y);
                    bfr[2 * p + 1][0] = __float_as_uint(bv.z);
                    bfr[2 * p + 1][1] = __float_as_uint(bv.w);
                }
            } else {
#pragma unroll
                for (int j = 0; j < 8; j++) {
                    if (BLAY == 0) {
                        const float* p = bs + (kb + tg) * 264 + wn + j * 8 + gid;
                        bfr[j][0] = __float_as_uint(p[0]);
                        bfr[j][1] = __float_as_uint(p[4 * 264]);
                    } else {
                        const float* p = bs + (wn + j * 8 + gid) * 36 + kb + tg;
                        bfr[j][0] = __float_as_uint(p[0]);
                        bfr[j][1] = __float_as_uint(p[4]);
                    }
                }
            }
#pragma unroll
            for (int i = 0; i < 4; i++)
#pragma unroll
                for (int j = 0; j < 8; j++)
                    mma_tf32(acc[i][j], afr[i], bfr[j]);
        }
    }

    // ---------------- epilogue ----------------
#pragma unroll
    for (int i = 0; i < 4; i++) {
        long mr = m0 + wm + i * 16 + gid;
#pragma unroll
        for (int j = 0; j < 8; j++) {
            long nc = n0 + wn + j * 8 + tg * 2;
            float v0 = acc[i][j][0], v1 = acc[i][j][1];
            float v2 = acc[i][j][2], v3 = acc[i][j][3];
            if (EPI == 1) {
                float b0 = bias[mr], b1 = bias[mr + 8];
                v0 += b0; v1 += b0; v2 += b1; v3 += b1;
                if (mr < relu_limit)     { v0 = fmaxf(v0, 0.f); v1 = fmaxf(v1, 0.f); }
                if (mr + 8 < relu_limit) { v2 = fmaxf(v2, 0.f); v3 = fmaxf(v3, 0.f); }
            } else if (EPI == 3) {
                const float* ax = aux + (long)blockIdx.z * aux_bs;
                float b0 = bias[mr], b1 = bias[mr + 8];
                const float2 r0 = *reinterpret_cast<const float2*>(ax + mr * ldc + nc);
                const float2 r1 = *reinterpret_cast<const float2*>(ax + (mr + 8) * ldc + nc);
                v0 += b0 + r0.x; v1 += b0 + r0.y;
                v2 += b1 + r1.x; v3 += b1 + r1.y;
            }
            if (ROUND) {
                v0 = f2tf_rna(v0); v1 = f2tf_rna(v1);
                v2 = f2tf_rna(v2); v3 = f2tf_rna(v3);
            }
            float2 s0; s0.x = v0; s0.y = v1;
            float2 s1; s1.x = v2; s1.y = v3;
            *reinterpret_cast<float2*>(C + mr * (long)ldc + nc)       = s0;
            *reinterpret_cast<float2*>(C + (mr + 8) * (long)ldc + nc) = s1;
        }
    }
}

// ---------------- row softmax (in place, rounded output) -----------------------
__global__ void __launch_bounds__(256)
softmax_kernel(float* __restrict__ attn)
{
    float* p = attn + (size_t)blockIdx.x * NN;
    const int t = threadIdx.x;
    float v[9];
    float mx = -1e30f;
#pragma unroll
    for (int i = 0; i < 9; i++) {
        v[i] = p[t + i * 256];
        mx = fmaxf(mx, v[i]);
    }
    __shared__ float red[8];
#pragma unroll
    for (int o = 16; o > 0; o >>= 1) mx = fmaxf(mx, __shfl_xor_sync(0xffffffffu, mx, o));
    if ((t & 31) == 0) red[t >> 5] = mx;
    __syncthreads();
    if (t == 0) {
        float m = red[0];
#pragma unroll
        for (int i = 1; i < 8; i++) m = fmaxf(m, red[i]);
        red[0] = m;
    }
    __syncthreads();
    mx = red[0];

    float s = 0.f;
#pragma unroll
    for (int i = 0; i < 9; i++) {
        v[i] = expf(v[i] - mx);
        s += v[i];
    }
#pragma unroll
    for (int o = 16; o > 0; o >>= 1) s += __shfl_xor_sync(0xffffffffu, s, o);
    __syncthreads();
    if ((t & 31) == 0) red[t >> 5] = s;
    __syncthreads();
    if (t == 0) {
        float m = 0.f;
#pragma unroll
        for (int i = 0; i < 8; i++) m += red[i];
        red[0] = m;
    }
    __syncthreads();
    float inv = 1.f / red[0];
#pragma unroll
    for (int i = 0; i < 9; i++) p[t + i * 256] = f2tf_rna(v[i] * inv);
}

// ---------------- launch ---------------------------------------------------------
extern "C" void kernel_launch(void* const* d_in, const int* in_sizes, int n_in,
                              void* d_out, int out_size)
{
    const float* x    = (const float*)d_in[0];
    const float* f_w  = (const float*)d_in[1];
    const float* f_b  = (const float*)d_in[2];
    const float* f_g  = (const float*)d_in[3];
    const float* f_be = (const float*)d_in[4];
    const float* f_m  = (const float*)d_in[5];
    const float* f_v  = (const float*)d_in[6];
    const float* g_w  = (const float*)d_in[7];
    const float* g_b  = (const float*)d_in[8];
    const float* g_g  = (const float*)d_in[9];
    const float* g_be = (const float*)d_in[10];
    const float* g_m  = (const float*)d_in[11];
    const float* g_v  = (const float*)d_in[12];
    const float* h_w  = (const float*)d_in[13];
    const float* h_b  = (const float*)d_in[14];
    const float* v_w  = (const float*)d_in[15];
    const float* v_b  = (const float*)d_in[16];

    float* out  = (float*)d_out;
    float* attn = out + (size_t)NB * CC * NN;

    float *wpk, *bfold, *vpk, *xpk, *fgh, *z;
    cudaGetSymbolAddress((void**)&wpk,   g_wpk);
    cudaGetSymbolAddress((void**)&bfold, g_bfold);
    cudaGetSymbolAddress((void**)&vpk,   g_vpk);
    cudaGetSymbolAddress((void**)&xpk,   g_xpk);
    cudaGetSymbolAddress((void**)&fgh,   g_fgh);
    cudaGetSymbolAddress((void**)&z,     g_z);

    cudaFuncSetAttribute(gemm_cp<1, 0, 1, 0, 1, 1>, cudaFuncAttributeMaxDynamicSharedMemorySize, GEMM_SMEM);
    cudaFuncSetAttribute(gemm_cp<0, 1, 0, 0, 0, 0>, cudaFuncAttributeMaxDynamicSharedMemorySize, GEMM_SMEM);
    cudaFuncSetAttribute(gemm_cp<0, 0, 0, 1, 0, 1>, cudaFuncAttributeMaxDynamicSharedMemorySize, GEMM_SMEM);
    cudaFuncSetAttribute(gemm_cp<1, 0, 0, 0, 3, 0>, cudaFuncAttributeMaxDynamicSharedMemorySize, GEMM_SMEM);

    // 0) prep: bias fold, packed weights, packed v_w, packed+rounded x
    prep_bias<<<(M1 + 255) / 256, 256>>>(f_b, f_g, f_be, f_m, f_v,
                                         g_b, g_g, g_be, g_m, g_v, h_b);
    packw_kernel<<<(M1 * CC / 4 + 255) / 256, 256>>>(f_w, f_g, f_v, g_w, g_g, g_v, h_w);
    packv_kernel<<<(CC * MID / 4 + 255) / 256, 256>>>(v_w);
    packx_kernel<<<(NB * NN * CC / 4 + 255) / 256, 256>>>(x);

    // 1) FGH = Wfold @ X  (packed A, packed B; bias + relu rows<1024, rounded)
    gemm_cp<1, 0, 1, 0, 1, 1><<<dim3(NN / 256, M1 / 128, NB), 256, GEMM_SMEM>>>(
        wpk, 0L, 0,
        xpk, (long)NN * CC, 0,
        fgh, (long)M1 * NN, NN,
        CC, bfold, 2 * MID, nullptr, 0L);

    // 2) scores = f^T @ g  (scale pre-folded into f)
    gemm_cp<0, 1, 0, 0, 0, 0><<<dim3(NN / 256, NN / 128, NB), 256, GEMM_SMEM>>>(
        fgh, (long)M1 * NN, NN,
        fgh + (size_t)MID * NN, (long)M1 * NN, NN,
        attn, (long)NN * NN, NN,
        MID, nullptr, 0, nullptr, 0L);

    // 3) softmax rows (in place, rounded)
    softmax_kernel<<<NB * NN, 256>>>(attn);

    // 4) z = h @ attn^T  (rounded output)
    gemm_cp<0, 0, 0, 1, 0, 1><<<dim3(NN / 256, MID / 128, NB), 256, GEMM_SMEM>>>(
        fgh + (size_t)2 * MID * NN, (long)M1 * NN, NN,
        attn, (long)NN * NN, NN,
        z, (long)MID * NN, NN,
        NN, nullptr, 0, nullptr, 0L);

    // 5) out = v_w @ z + v_b + x  (packed A)
    gemm_cp<1, 0, 0, 0, 3, 0><<<dim3(NN / 256, CC / 128, NB), 256, GEMM_SMEM>>>(
        vpk, 0L, 0,
        z, (long)MID * NN, NN,
        out, (long)CC * NN, NN,
        MID, v_b, 0, x, (long)CC * NN);
}

// round 7
// speedup vs baseline: 1.9801x; 1.0534x over previous
#include <cuda_runtime.h>
#include <cstdint>
#include <cmath>

#define NB   8
#define CC   2048
#define NN   2304
#define MID  512
#define M1   1536

// ---------------- scratch ----------------------------------------------------
__device__ float g_wpk[(size_t)M1 * CC];        // packed folded weights (GEMM1 A)
__device__ float g_bfold[M1];
__device__ float g_vpk[(size_t)CC * MID];       // packed rounded v_w (GEMM5 A)
__device__ float g_xpk[(size_t)NB * NN * CC];   // packed rounded x (GEMM1 B)
__device__ float g_fA[(size_t)NB * NN * MID];   // f, GEMM2-A-packed
__device__ float g_gB[(size_t)NB * NN * MID];   // g, GEMM2-B-packed
__device__ float g_hA[(size_t)NB * MID * NN];   // h, GEMM4-A-packed
__device__ float g_aB[(size_t)NB * NN * NN];    // attn, GEMM4-B-packed
__device__ float g_zB[(size_t)NB * MID * NN];   // z, GEMM5-B-packed

// ---------------- helpers ------------------------------------------------------
__device__ __forceinline__ float f2tf_rna(float x) {
    uint32_t u;
    asm("cvt.rna.tf32.f32 %0, %1;" : "=r"(u) : "f"(x));
    return __uint_as_float(u);
}
__device__ __forceinline__ uint32_t smem_u32(const void* p) {
    uint32_t a;
    asm("{ .reg .u64 t; cvta.to.shared.u64 t, %1; cvt.u32.u64 %0, t; }" : "=r"(a) : "l"(p));
    return a;
}
__device__ __forceinline__ void mma_tf32(float* c, const uint32_t* a, const uint32_t* b) {
    asm volatile(
        "mma.sync.aligned.m16n8k8.row.col.f32.tf32.tf32.f32 "
        "{%0,%1,%2,%3}, {%4,%5,%6,%7}, {%8,%9}, {%0,%1,%2,%3};\n"
        : "+f"(c[0]), "+f"(c[1]), "+f"(c[2]), "+f"(c[3])
        : "r"(a[0]), "r"(a[1]), "r"(a[2]), "r"(a[3]), "r"(b[0]), "r"(b[1]));
}
__device__ __forceinline__ void cp16(uint32_t saddr, const void* gaddr) {
    asm volatile("cp.async.cg.shared.global [%0], [%1], 16;" :: "r"(saddr), "l"(gaddr) : "memory");
}

// A-pack: slab (mblk*KT+kt) of 4096 floats = [ks(4)][mt(8)][lane(32)][e(4)]
// float4 elems {A[m][k], A[m+8][k], A[m][k+4], A[m+8][k+4]},
// m = mblk*128+mt*16+gid, k = kt*32+ks*8+tg, lane = gid*4+tg.
__device__ __forceinline__ int addrA(int m, int k, int KT) {
    int mblk = m >> 7, mt = (m >> 4) & 7, gid = m & 7, e1 = (m >> 3) & 1;
    int kt = k >> 5, ks = (k >> 3) & 3, tg = k & 3, e2 = (k >> 2) & 1;
    return ((mblk * KT + kt) << 12) + ((((ks << 3) + mt) << 5) + (gid << 2) + tg) * 4 + e1 + (e2 << 1);
}
// B-pack: slab (nblk*KT+kt) of 8192 floats = [ks(4)][ntp(16)][lane(32)][e(4)]
// float4 elems {B[k][na], B[k+4][na], B[k][na+8], B[k+4][na+8]},
// na = nblk*256+ntp*16+gid, k = kt*32+ks*8+tg, lane = gid*4+tg.
__device__ __forceinline__ int addrB(int k, int n, int KT) {
    int nblk = n >> 8, gid = n & 7, q = (n >> 3) & 31, ntp = q >> 1, en = q & 1;
    int kt = k >> 5, ks = (k >> 3) & 3, tg = k & 3, ek = (k >> 2) & 1;
    return ((nblk * KT + kt) << 13) + ((((ks << 4) + ntp) << 5) + (gid << 2) + tg) * 4 + ek + (en << 1);
}

// ---------------- prep kernels -------------------------------------------------
__global__ void prep_bias(
    const float* __restrict__ f_b, const float* __restrict__ f_g,
    const float* __restrict__ f_be, const float* __restrict__ f_m,
    const float* __restrict__ f_v,
    const float* __restrict__ g_b, const float* __restrict__ g_g,
    const float* __restrict__ g_be, const float* __restrict__ g_m,
    const float* __restrict__ g_v,
    const float* __restrict__ h_b)
{
    const float SC = 0.044194173824159223f;
    int r = blockIdx.x * 256 + threadIdx.x;
    if (r >= M1) return;
    float b;
    if (r < MID) {
        float inv = f_g[r] / sqrtf(f_v[r] + 1e-5f);
        b = (f_b[r] * inv + f_be[r] - f_m[r] * inv) * SC;
    } else if (r < 2 * MID) {
        int rr = r - MID;
        float inv = g_g[rr] / sqrtf(g_v[rr] + 1e-5f);
        b = g_b[rr] * inv + g_be[rr] - g_m[rr] * inv;
    } else {
        b = h_b[r - 2 * MID];
    }
    g_bfold[r] = b;
}

__global__ void packw_kernel(
    const float* __restrict__ f_w, const float* __restrict__ f_g, const float* __restrict__ f_v,
    const float* __restrict__ g_w, const float* __restrict__ g_g, const float* __restrict__ g_v,
    const float* __restrict__ h_w)
{
    const float SC = 0.044194173824159223f;
    int idx = blockIdx.x * 256 + threadIdx.x;
    if (idx >= M1 * CC / 4) return;
    int lane = idx & 31;
    int ksmt = (idx >> 5) & 31;
    int kt   = (idx >> 10) & 63;
    int mblk = idx >> 16;
    int ks = ksmt >> 3, mt = ksmt & 7;
    int gid = lane >> 2, tg = lane & 3;
    float4 v;
#pragma unroll
    for (int e = 0; e < 4; e++) {
        int m = mblk * 128 + mt * 16 + gid + (e & 1) * 8;
        int c = kt * 32 + ks * 8 + tg + (e >> 1) * 4;
        float w;
        if (m < MID) {
            float inv = f_g[m] / sqrtf(f_v[m] + 1e-5f);
            w = f_w[m * CC + c] * inv * SC;
        } else if (m < 2 * MID) {
            int rr = m - MID;
            float inv = g_g[rr] / sqrtf(g_v[rr] + 1e-5f);
            w = g_w[rr * CC + c] * inv;
        } else {
            w = h_w[(m - 2 * MID) * CC + c];
        }
        (&v.x)[e] = f2tf_rna(w);
    }
    reinterpret_cast<float4*>(g_wpk)[idx] = v;
}

__global__ void packv_kernel(const float* __restrict__ v_w)
{
    int idx = blockIdx.x * 256 + threadIdx.x;
    if (idx >= CC * MID / 4) return;
    int lane = idx & 31;
    int ksmt = (idx >> 5) & 31;
    int kt   = (idx >> 10) & 15;
    int mblk = idx >> 14;
    int ks = ksmt >> 3, mt = ksmt & 7;
    int gid = lane >> 2, tg = lane & 3;
    float4 v;
#pragma unroll
    for (int e = 0; e < 4; e++) {
        int m = mblk * 128 + mt * 16 + gid + (e & 1) * 8;
        int c = kt * 32 + ks * 8 + tg + (e >> 1) * 4;
        (&v.x)[e] = f2tf_rna(v_w[m * MID + c]);
    }
    reinterpret_cast<float4*>(g_vpk)[idx] = v;
}

__global__ void packx_kernel(const float* __restrict__ x)
{
    int idx = blockIdx.x * 256 + threadIdx.x;       // total 9437184, divisible by 256
    int lane = idx & 31;
    int ntp  = (idx >> 5) & 15;
    int ks   = (idx >> 9) & 3;
    int kt   = (idx >> 11) & 63;
    int t    = idx >> 17;
    int nblk = t % 9;
    int b    = t / 9;
    int gid = lane >> 2, tg = lane & 3;
    const float* xb = x + (size_t)b * CC * NN;
    float4 v;
#pragma unroll
    for (int e = 0; e < 4; e++) {
        int c = kt * 32 + ks * 8 + tg + (e & 1) * 4;
        int n = nblk * 256 + (ntp * 2 + (e >> 1)) * 8 + gid;
        (&v.x)[e] = f2tf_rna(xb[(size_t)c * NN + n]);
    }
    reinterpret_cast<float4*>(g_xpk)[idx] = v;
}

// ---------------- packed tf32 GEMM, 128x256 CTA tile ---------------------------
// C[m][n] = sum_k A(m,k)*B(k,n); A,B fragment-packed.
// EPI: 0 none ; 1 +bias[m], relu if m<relu_limit ; 3 +bias[m]+aux (residual)
// OUT: 0 canonical C ; 1 GEMM1 triple (fA/gB/hA) ; 2 zB pack
constexpr int ST = 4;
constexpr int A_FLT = 4096;
constexpr int B_FLT = 8192;
constexpr int STAGE_FLT = A_FLT + B_FLT;        // 12288
constexpr int GEMM_SMEM = ST * STAGE_FLT * 4;   // 196608 B

template <int EPI, int ROUND, int OUT>
__global__ void __launch_bounds__(256, 1)
gemm_pk(const float* __restrict__ A, long a_bs,
        const float* __restrict__ B, long b_bs,
        float* __restrict__ C, long c_bs, int ldc,
        int K,
        const float* __restrict__ bias, int relu_limit,
        const float* __restrict__ aux, long aux_bs,
        float* __restrict__ o0, float* __restrict__ o1, float* __restrict__ o2)
{
    extern __shared__ float sm[];
    const uint32_t sm_base = smem_u32(sm);

    const int tid  = threadIdx.x;
    const int lane = tid & 31;
    const int wid  = tid >> 5;
    const int gid  = lane >> 2;
    const int tg   = lane & 3;
    const int wm   = (wid & 1) * 64;
    const int wn   = (wid >> 1) * 64;
    const int m0   = blockIdx.y * 128;
    const int n0   = blockIdx.x * 256;
    const int bz   = blockIdx.z;

    A += (long)bz * a_bs;
    B += (long)bz * b_bs;

    const int KT = K / 32;

    float acc[4][8][4];
#pragma unroll
    for (int i = 0; i < 4; i++)
#pragma unroll
        for (int j = 0; j < 8; j++)
#pragma unroll
            for (int r = 0; r < 4; r++) acc[i][j][r] = 0.0f;

    auto load_stage = [&](int s, int kt) {
        const uint32_t sa = sm_base + (s * STAGE_FLT) * 4;
        const uint32_t sb = sa + A_FLT * 4;
        const float* ga = A + ((long)blockIdx.y * KT + kt) * 4096;
#pragma unroll
        for (int i = 0; i < 4; i++) {
            int idx = tid + i * 256;
            cp16(sa + idx * 16, ga + idx * 4);
        }
        const float* gb = B + ((long)blockIdx.x * KT + kt) * 8192;
#pragma unroll
        for (int i = 0; i < 8; i++) {
            int idx = tid + i * 256;
            cp16(sb + idx * 16, gb + idx * 4);
        }
    };

#pragma unroll
    for (int kt = 0; kt < ST - 1; kt++) {
        if (kt < KT) load_stage(kt, kt);
        asm volatile("cp.async.commit_group;" ::: "memory");
    }

    for (int kt = 0; kt < KT; kt++) {
        const int s = kt % ST;
        asm volatile("cp.async.wait_group %0;" :: "n"(ST - 2) : "memory");
        __syncthreads();

        const int ktl = kt + ST - 1;
        if (ktl < KT) load_stage(ktl % ST, ktl);
        asm volatile("cp.async.commit_group;" ::: "memory");

        const float* as = sm + s * STAGE_FLT;
        const float* bs = as + A_FLT;
#pragma unroll
        for (int ks = 0; ks < 4; ks++) {
            uint32_t afr[4][4], bfr[8][2];
#pragma unroll
            for (int i = 0; i < 4; i++) {
                const float4 av = reinterpret_cast<const float4*>(as)
                    [(ks * 8 + (wid & 1) * 4 + i) * 32 + lane];
                afr[i][0] = __float_as_uint(av.x);
                afr[i][1] = __float_as_uint(av.y);
                afr[i][2] = __float_as_uint(av.z);
                afr[i][3] = __float_as_uint(av.w);
            }
#pragma unroll
            for (int p = 0; p < 4; p++) {
                const float4 bv = reinterpret_cast<const float4*>(bs)
                    [(ks * 16 + (wid >> 1) * 4 + p) * 32 + lane];
                bfr[2 * p][0]     = __float_as_uint(bv.x);
                bfr[2 * p][1]     = __float_as_uint(bv.y);
                bfr[2 * p + 1][0] = __float_as_uint(bv.z);
                bfr[2 * p + 1][1] = __float_as_uint(bv.w);
            }
#pragma unroll
            for (int i = 0; i < 4; i++)
#pragma unroll
                for (int j = 0; j < 8; j++)
                    mma_tf32(acc[i][j], afr[i], bfr[j]);
        }
    }

    // ---------------- epilogue ----------------
#pragma unroll
    for (int i = 0; i < 4; i++) {
        int mr = m0 + wm + i * 16 + gid;
#pragma unroll
        for (int j = 0; j < 8; j++) {
            int nc = n0 + wn + j * 8 + tg * 2;
            float v0 = acc[i][j][0], v1 = acc[i][j][1];
            float v2 = acc[i][j][2], v3 = acc[i][j][3];
            if (EPI == 1) {
                float b0 = bias[mr], b1 = bias[mr + 8];
                v0 += b0; v1 += b0; v2 += b1; v3 += b1;
                if (mr < relu_limit)     { v0 = fmaxf(v0, 0.f); v1 = fmaxf(v1, 0.f); }
                if (mr + 8 < relu_limit) { v2 = fmaxf(v2, 0.f); v3 = fmaxf(v3, 0.f); }
            } else if (EPI == 3) {
                const float* ax = aux + (long)bz * aux_bs;
                float b0 = bias[mr], b1 = bias[mr + 8];
                const float2 r0 = *reinterpret_cast<const float2*>(ax + (long)mr * ldc + nc);
                const float2 r1 = *reinterpret_cast<const float2*>(ax + (long)(mr + 8) * ldc + nc);
                v0 += b0 + r0.x; v1 += b0 + r0.y;
                v2 += b1 + r1.x; v3 += b1 + r1.y;
            }
            if (ROUND) {
                v0 = f2tf_rna(v0); v1 = f2tf_rna(v1);
                v2 = f2tf_rna(v2); v3 = f2tf_rna(v3);
            }
            if (OUT == 0) {
                float* Cb = C + (long)bz * c_bs;
                float2 s0; s0.x = v0; s0.y = v1;
                float2 s1; s1.x = v2; s1.y = v3;
                *reinterpret_cast<float2*>(Cb + (long)mr * ldc + nc)       = s0;
                *reinterpret_cast<float2*>(Cb + (long)(mr + 8) * ldc + nc) = s1;
            } else if (OUT == 1) {
                if (mr < MID) {                               // f -> GEMM2 A-pack
                    float* base = o0 + (size_t)bz * NN * MID;
                    base[addrA(nc,     mr,     16)] = v0;
                    base[addrA(nc + 1, mr,     16)] = v1;
                    base[addrA(nc,     mr + 8, 16)] = v2;
                    base[addrA(nc + 1, mr + 8, 16)] = v3;
                } else if (mr < 2 * MID) {                    // g -> GEMM2 B-pack
                    float* base = o1 + (size_t)bz * NN * MID;
                    int k = mr - MID;
                    base[addrB(k,     nc,     16)] = v0;
                    base[addrB(k,     nc + 1, 16)] = v1;
                    base[addrB(k + 8, nc,     16)] = v2;
                    base[addrB(k + 8, nc + 1, 16)] = v3;
                } else {                                      // h -> GEMM4 A-pack
                    float* base = o2 + (size_t)bz * MID * NN;
                    int m = mr - 2 * MID;
                    base[addrA(m,     nc,     72)] = v0;
                    base[addrA(m,     nc + 1, 72)] = v1;
                    base[addrA(m + 8, nc,     72)] = v2;
                    base[addrA(m + 8, nc + 1, 72)] = v3;
                }
            } else {                                          // OUT==2: z -> GEMM5 B-pack
                float* base = o0 + (size_t)bz * MID * NN;
                base[addrB(mr,     nc,     16)] = v0;
                base[addrB(mr,     nc + 1, 16)] = v1;
                base[addrB(mr + 8, nc,     16)] = v2;
                base[addrB(mr + 8, nc + 1, 16)] = v3;
            }
        }
    }
}

// ---------------- row softmax: canonical in-place + packed copy ------------------
__global__ void __launch_bounds__(256)
softmax_kernel(float* __restrict__ attn, float* __restrict__ apk)
{
    const int row = blockIdx.x;
    const int b = row / NN, nr = row % NN;
    float* p = attn + (size_t)row * NN;
    float* pk = apk + (size_t)b * NN * NN;
    const int t = threadIdx.x;
    float v[9];
    float mx = -1e30f;
#pragma unroll
    for (int i = 0; i < 9; i++) {
        v[i] = p[t + i * 256];
        mx = fmaxf(mx, v[i]);
    }
    __shared__ float red[8];
#pragma unroll
    for (int o = 16; o > 0; o >>= 1) mx = fmaxf(mx, __shfl_xor_sync(0xffffffffu, mx, o));
    if ((t & 31) == 0) red[t >> 5] = mx;
    __syncthreads();
    if (t == 0) {
        float m = red[0];
#pragma unroll
        for (int i = 1; i < 8; i++) m = fmaxf(m, red[i]);
        red[0] = m;
    }
    __syncthreads();
    mx = red[0];

    float s = 0.f;
#pragma unroll
    for (int i = 0; i < 9; i++) {
        v[i] = expf(v[i] - mx);
        s += v[i];
    }
#pragma unroll
    for (int o = 16; o > 0; o >>= 1) s += __shfl_xor_sync(0xffffffffu, s, o);
    __syncthreads();
    if ((t & 31) == 0) red[t >> 5] = s;
    __syncthreads();
    if (t == 0) {
        float m = 0.f;
#pragma unroll
        for (int i = 0; i < 8; i++) m += red[i];
        red[0] = m;
    }
    __syncthreads();
    float inv = 1.f / red[0];
#pragma unroll
    for (int i = 0; i < 9; i++) {
        float o = f2tf_rna(v[i] * inv);
        p[t + i * 256] = o;                       // canonical (required output)
        pk[addrB(t + i * 256, nr, 72)] = o;       // packed for GEMM4 B
    }
}

// ---------------- launch ---------------------------------------------------------
extern "C" void kernel_launch(void* const* d_in, const int* in_sizes, int n_in,
                              void* d_out, int out_size)
{
    const float* x    = (const float*)d_in[0];
    const float* f_w  = (const float*)d_in[1];
    const float* f_b  = (const float*)d_in[2];
    const float* f_g  = (const float*)d_in[3];
    const float* f_be = (const float*)d_in[4];
    const float* f_m  = (const float*)d_in[5];
    const float* f_v  = (const float*)d_in[6];
    const float* g_w  = (const float*)d_in[7];
    const float* g_b  = (const float*)d_in[8];
    const float* g_g  = (const float*)d_in[9];
    const float* g_be = (const float*)d_in[10];
    const float* g_m  = (const float*)d_in[11];
    const float* g_v  = (const float*)d_in[12];
    const float* h_w  = (const float*)d_in[13];
    const float* h_b  = (const float*)d_in[14];
    const float* v_w  = (const float*)d_in[15];
    const float* v_b  = (const float*)d_in[16];

    float* out  = (float*)d_out;
    float* attn = out + (size_t)NB * CC * NN;

    float *wpk, *bfold, *vpk, *xpk, *fA, *gB, *hA, *aB, *zB;
    cudaGetSymbolAddress((void**)&wpk,   g_wpk);
    cudaGetSymbolAddress((void**)&bfold, g_bfold);
    cudaGetSymbolAddress((void**)&vpk,   g_vpk);
    cudaGetSymbolAddress((void**)&xpk,   g_xpk);
    cudaGetSymbolAddress((void**)&fA,    g_fA);
    cudaGetSymbolAddress((void**)&gB,    g_gB);
    cudaGetSymbolAddress((void**)&hA,    g_hA);
    cudaGetSymbolAddress((void**)&aB,    g_aB);
    cudaGetSymbolAddress((void**)&zB,    g_zB);

    cudaFuncSetAttribute(gemm_pk<1, 1, 1>, cudaFuncAttributeMaxDynamicSharedMemorySize, GEMM_SMEM);
    cudaFuncSetAttribute(gemm_pk<0, 0, 0>, cudaFuncAttributeMaxDynamicSharedMemorySize, GEMM_SMEM);
    cudaFuncSetAttribute(gemm_pk<0, 1, 2>, cudaFuncAttributeMaxDynamicSharedMemorySize, GEMM_SMEM);
    cudaFuncSetAttribute(gemm_pk<3, 0, 0>, cudaFuncAttributeMaxDynamicSharedMemorySize, GEMM_SMEM);

    // 0) prep
    prep_bias<<<(M1 + 255) / 256, 256>>>(f_b, f_g, f_be, f_m, f_v,
                                         g_b, g_g, g_be, g_m, g_v, h_b);
    packw_kernel<<<(M1 * CC / 4 + 255) / 256, 256>>>(f_w, f_g, f_v, g_w, g_g, g_v, h_w);
    packv_kernel<<<(CC * MID / 4 + 255) / 256, 256>>>(v_w);
    packx_kernel<<<(NB * NN * CC / 4 + 255) / 256, 256>>>(x);

    // 1) FGH = Wfold @ X  -> f/g/h in consumer-packed layouts (bias+relu+round)
    gemm_pk<1, 1, 1><<<dim3(NN / 256, M1 / 128, NB), 256, GEMM_SMEM>>>(
        wpk, 0L, xpk, (long)NN * CC,
        nullptr, 0L, NN, CC, bfold, 2 * MID, nullptr, 0L,
        fA, gB, hA);

    // 2) scores = f^T @ g -> canonical logits in attn region
    gemm_pk<0, 0, 0><<<dim3(NN / 256, NN / 128, NB), 256, GEMM_SMEM>>>(
        fA, (long)NN * MID, gB, (long)NN * MID,
        attn, (long)NN * NN, NN, MID, nullptr, 0, nullptr, 0L,
        nullptr, nullptr, nullptr);

    // 3) softmax (canonical in place + packed copy)
    softmax_kernel<<<NB * NN, 256>>>(attn, aB);

    // 4) z = h @ attn^T -> GEMM5 B-pack (round)
    gemm_pk<0, 1, 2><<<dim3(NN / 256, MID / 128, NB), 256, GEMM_SMEM>>>(
        hA, (long)MID * NN, aB, (long)NN * NN,
        nullptr, 0L, NN, NN, nullptr, 0, nullptr, 0L,
        zB, nullptr, nullptr);

    // 5) out = v_w @ z + v_b + x
    gemm_pk<3, 0, 0><<<dim3(NN / 256, CC / 128, NB), 256, GEMM_SMEM>>>(
        vpk, 0L, zB, (long)MID * NN,
        out, (long)CC * NN, NN, MID, v_b, 0, x, (long)CC * NN,
        nullptr, nullptr, nullptr);
}

// round 9
// speedup vs baseline: 3.1012x; 1.5662x over previous
#include <cuda_runtime.h>
#include <cuda_fp16.h>
#include <cstdint>
#include <cmath>

#define NB   8
#define CC   2048
#define NN   2304
#define MID  512
#define M1   1536

// ---------------- scratch (fp16 packed operands) -------------------------------
__device__ __half g_wpk[(size_t)M1 * CC];        // packed folded weights (GEMM1 A)
__device__ float  g_bfold[M1];
__device__ __half g_vpk[(size_t)CC * MID];       // packed v_w (GEMM5 A)
__device__ __half g_xpk[(size_t)NB * NN * CC];   // packed x (GEMM1 B)
__device__ __half g_fA[(size_t)NB * NN * MID];   // f, GEMM2-A-packed
__device__ __half g_gB[(size_t)NB * NN * MID];   // g, GEMM2-B-packed
__device__ __half g_hA[(size_t)NB * MID * NN];   // h, GEMM4-A-packed
__device__ __half g_aB[(size_t)NB * NN * NN];    // attn, GEMM4-B-packed
__device__ __half g_zB[(size_t)NB * MID * NN];   // z, GEMM5-B-packed

// ---------------- helpers ------------------------------------------------------
__device__ __forceinline__ uint32_t smem_u32(const void* p) {
    uint32_t a;
    asm("{ .reg .u64 t; cvta.to.shared.u64 t, %1; cvt.u32.u64 %0, t; }" : "=r"(a) : "l"(p));
    return a;
}
__device__ __forceinline__ void mma_f16(float* c, const uint32_t* a, const uint32_t* b) {
    asm volatile(
        "mma.sync.aligned.m16n8k16.row.col.f32.f16.f16.f32 "
        "{%0,%1,%2,%3}, {%4,%5,%6,%7}, {%8,%9}, {%0,%1,%2,%3};\n"
        : "+f"(c[0]), "+f"(c[1]), "+f"(c[2]), "+f"(c[3])
        : "r"(a[0]), "r"(a[1]), "r"(a[2]), "r"(a[3]), "r"(b[0]), "r"(b[1]));
}
__device__ __forceinline__ void cp16(uint32_t saddr, const void* gaddr) {
    asm volatile("cp.async.cg.shared.global [%0], [%1], 16;" :: "r"(saddr), "l"(gaddr) : "memory");
}

// A-pack (halves): slab(mblk*KT32+kt32) = [ks2(2)][mt(8)][lane(32)] uint4 (8 halves)
// lane = gid*4+tg; uint4 = rows {gid,gid+8} x k {2tg,2tg+1} (+8 for upper uint32 pair)
__device__ __forceinline__ long addrA_h(int m, int k, int KT32) {
    int slab = (m >> 7) * KT32 + (k >> 5);
    int ks2  = (k >> 4) & 1;
    int mt = (m >> 4) & 7, gid = m & 7, rh = (m >> 3) & 1;
    int kk = k & 15, tg = (kk >> 1) & 3, hb = kk & 1, kh = (kk >> 3) & 1;
    int lane = gid * 4 + tg, u = rh + 2 * kh;
    return (long)slab * 4096 + ks2 * 2048 + mt * 256 + lane * 8 + u * 2 + hb;
}
// B-pack (halves): slab(nblk*KT32+kt32) = [ks2(2)][nt(32)][lane(32)] uint2 (4 halves)
// lane = gid*4+tg; uint2 = col gid, k {2tg,2tg+1} and {+8}
__device__ __forceinline__ long addrB_h(int k, int n, int KT32) {
    int slab = (n >> 8) * KT32 + (k >> 5);
    int ks2  = (k >> 4) & 1;
    int nt = (n >> 3) & 31, gid = n & 7;
    int kk = k & 15, tg = (kk >> 1) & 3, hb = kk & 1, u = (kk >> 3) & 1;
    int lane = gid * 4 + tg;
    return (long)slab * 8192 + ks2 * 4096 + nt * 128 + lane * 4 + u * 2 + hb;
}

// ---------------- prep kernels -------------------------------------------------
__global__ void prep_bias(
    const float* __restrict__ f_b, const float* __restrict__ f_g,
    const float* __restrict__ f_be, const float* __restrict__ f_m,
    const float* __restrict__ f_v,
    const float* __restrict__ g_b, const float* __restrict__ g_g,
    const float* __restrict__ g_be, const float* __restrict__ g_m,
    const float* __restrict__ g_v,
    const float* __restrict__ h_b)
{
    const float SC = 0.044194173824159223f;
    int r = blockIdx.x * 256 + threadIdx.x;
    if (r >= M1) return;
    float b;
    if (r < MID) {
        float inv = f_g[r] / sqrtf(f_v[r] + 1e-5f);
        b = (f_b[r] * inv + f_be[r] - f_m[r] * inv) * SC;
    } else if (r < 2 * MID) {
        int rr = r - MID;
        float inv = g_g[rr] / sqrtf(g_v[rr] + 1e-5f);
        b = g_b[rr] * inv + g_be[rr] - g_m[rr] * inv;
    } else {
        b = h_b[r - 2 * MID];
    }
    g_bfold[r] = b;
}

// one uint4 (8 halves) per thread
__global__ void packw_kernel(
    const float* __restrict__ f_w, const float* __restrict__ f_g, const float* __restrict__ f_v,
    const float* __restrict__ g_w, const float* __restrict__ g_g, const float* __restrict__ g_v,
    const float* __restrict__ h_w)
{
    const float SC = 0.044194173824159223f;
    int idx = blockIdx.x * 256 + threadIdx.x;     // total M1*CC/8 = 393216
    if (idx >= M1 * CC / 8) return;
    int lane = idx & 31, mt = (idx >> 5) & 7, ks2 = (idx >> 8) & 1;
    int kt = (idx >> 9) & 63, mblk = idx >> 15;
    int gid = lane >> 2, tg = lane & 3;
    __half h8[8];
#pragma unroll
    for (int u = 0; u < 4; u++)
#pragma unroll
        for (int hb = 0; hb < 2; hb++) {
            int m = mblk * 128 + mt * 16 + gid + (u & 1) * 8;
            int k = kt * 32 + ks2 * 16 + (u >> 1) * 8 + tg * 2 + hb;
            float w;
            if (m < MID) {
                float inv = f_g[m] / sqrtf(f_v[m] + 1e-5f);
                w = f_w[m * CC + k] * inv * SC;
            } else if (m < 2 * MID) {
                int rr = m - MID;
                float inv = g_g[rr] / sqrtf(g_v[rr] + 1e-5f);
                w = g_w[rr * CC + k] * inv;
            } else {
                w = h_w[(m - 2 * MID) * CC + k];
            }
            h8[u * 2 + hb] = __float2half_rn(w);
        }
    reinterpret_cast<uint4*>(g_wpk)[idx] = *reinterpret_cast<uint4*>(h8);
}

__global__ void packv_kernel(const float* __restrict__ v_w)
{
    int idx = blockIdx.x * 256 + threadIdx.x;     // total CC*MID/8 = 131072
    if (idx >= CC * MID / 8) return;
    int lane = idx & 31, mt = (idx >> 5) & 7, ks2 = (idx >> 8) & 1;
    int kt = (idx >> 9) & 15, mblk = idx >> 13;
    int gid = lane >> 2, tg = lane & 3;
    __half h8[8];
#pragma unroll
    for (int u = 0; u < 4; u++)
#pragma unroll
        for (int hb = 0; hb < 2; hb++) {
            int m = mblk * 128 + mt * 16 + gid + (u & 1) * 8;
            int k = kt * 32 + ks2 * 16 + (u >> 1) * 8 + tg * 2 + hb;
            h8[u * 2 + hb] = __float2half_rn(v_w[m * MID + k]);
        }
    reinterpret_cast<uint4*>(g_vpk)[idx] = *reinterpret_cast<uint4*>(h8);
}

// one uint2 (4 halves) per thread
__global__ void packx_kernel(const float* __restrict__ x)
{
    int idx = blockIdx.x * 256 + threadIdx.x;     // total NB*NN*CC/4 = 9437184
    int lane = idx & 31, nt = (idx >> 5) & 31, ks2 = (idx >> 10) & 1;
    int kt = (idx >> 11) & 63;
    int t = idx >> 17;                            // 0..71
    int nblk = t % 9, b = t / 9;
    int gid = lane >> 2, tg = lane & 3;
    const float* xb = x + (size_t)b * CC * NN;
    int n = nblk * 256 + nt * 8 + gid;
    __half h4[4];
#pragma unroll
    for (int u = 0; u < 2; u++)
#pragma unroll
        for (int hb = 0; hb < 2; hb++) {
            int k = kt * 32 + ks2 * 16 + u * 8 + tg * 2 + hb;
            h4[u * 2 + hb] = __float2half_rn(xb[(size_t)k * NN + n]);
        }
    reinterpret_cast<uint2*>(g_xpk)[idx] = *reinterpret_cast<uint2*>(h4);
}

// ---------------- packed fp16 GEMM, 128x256 CTA tile ---------------------------
// C[m][n] = sum_k A(m,k)*B(k,n); A,B fragment-packed fp16, fp32 accum.
// EPI: 0 none ; 1 +bias[m], relu if m<relu_limit ; 3 +bias[m]+aux (residual)
// OUT: 0 canonical fp32 C ; 1 GEMM1 triple (fA/gB/hA) ; 2 zB pack
constexpr int ST = 6;
constexpr int A_HALF = 4096;                     // 128 x 32k halves
constexpr int B_HALF = 8192;                     // 256 x 32k halves
constexpr int STAGE_HALF = A_HALF + B_HALF;      // 12288 halves = 24KB
constexpr int GEMM_SMEM = ST * STAGE_HALF * 2;   // 147456 B

template <int EPI, int OUT>
__global__ void __launch_bounds__(256, 1)
gemm_h(const __half* __restrict__ A, long a_bs,
       const __half* __restrict__ B, long b_bs,
       float* __restrict__ C, long c_bs, int ldc,
       int K,
       const float* __restrict__ bias, int relu_limit,
       const float* __restrict__ aux, long aux_bs,
       __half* __restrict__ o0, __half* __restrict__ o1, __half* __restrict__ o2)
{
    extern __shared__ __half sm[];
    const uint32_t sm_base = smem_u32(sm);

    const int tid  = threadIdx.x;
    const int lane = tid & 31;
    const int wid  = tid >> 5;
    const int gid  = lane >> 2;
    const int tg   = lane & 3;
    const int wm   = (wid & 1) * 64;
    const int wn   = (wid >> 1) * 64;
    const int m0   = blockIdx.y * 128;
    const int n0   = blockIdx.x * 256;
    const int bz   = blockIdx.z;

    A += (long)bz * a_bs;
    B += (long)bz * b_bs;

    const int KT = K / 32;

    float acc[4][8][4];
#pragma unroll
    for (int i = 0; i < 4; i++)
#pragma unroll
        for (int j = 0; j < 8; j++)
#pragma unroll
            for (int r = 0; r < 4; r++) acc[i][j][r] = 0.0f;

    auto load_stage = [&](int s, int kt) {
        const uint32_t sa = sm_base + s * STAGE_HALF * 2;
        const uint32_t sb = sa + A_HALF * 2;
        const __half* ga = A + ((long)blockIdx.y * KT + kt) * 4096;
#pragma unroll
        for (int i = 0; i < 2; i++) {
            int idx = tid + i * 256;
            cp16(sa + idx * 16, ga + idx * 8);
        }
        const __half* gb = B + ((long)blockIdx.x * KT + kt) * 8192;
#pragma unroll
        for (int i = 0; i < 4; i++) {
            int idx = tid + i * 256;
            cp16(sb + idx * 16, gb + idx * 8);
        }
    };

#pragma unroll
    for (int kt = 0; kt < ST - 1; kt++) {
        if (kt < KT) load_stage(kt, kt);
        asm volatile("cp.async.commit_group;" ::: "memory");
    }

    for (int kt = 0; kt < KT; kt++) {
        const int s = kt % ST;
        asm volatile("cp.async.wait_group %0;" :: "n"(ST - 2) : "memory");
        __syncthreads();

        const int ktl = kt + ST - 1;
        if (ktl < KT) load_stage(ktl % ST, ktl);
        asm volatile("cp.async.commit_group;" ::: "memory");

        const __half* as = sm + s * STAGE_HALF;
        const __half* bs = as + A_HALF;
        const uint4* A4 = reinterpret_cast<const uint4*>(as);
        const uint2* B2 = reinterpret_cast<const uint2*>(bs);
#pragma unroll
        for (int ks2 = 0; ks2 < 2; ks2++) {
            uint32_t afr[4][4], bfr[8][2];
#pragma unroll
            for (int i = 0; i < 4; i++) {
                const uint4 av = A4[(ks2 * 8 + (wid & 1) * 4 + i) * 32 + lane];
                afr[i][0] = av.x; afr[i][1] = av.y;
                afr[i][2] = av.z; afr[i][3] = av.w;
            }
#pragma unroll
            for (int j = 0; j < 8; j++) {
                const uint2 bv = B2[(ks2 * 32 + (wid >> 1) * 8 + j) * 32 + lane];
                bfr[j][0] = bv.x; bfr[j][1] = bv.y;
            }
#pragma unroll
            for (int i = 0; i < 4; i++)
#pragma unroll
                for (int j = 0; j < 8; j++)
                    mma_f16(acc[i][j], afr[i], bfr[j]);
        }
    }

    // ---------------- epilogue ----------------
#pragma unroll
    for (int i = 0; i < 4; i++) {
        int mr = m0 + wm + i * 16 + gid;
#pragma unroll
        for (int j = 0; j < 8; j++) {
            int nc = n0 + wn + j * 8 + tg * 2;
            float v0 = acc[i][j][0], v1 = acc[i][j][1];
            float v2 = acc[i][j][2], v3 = acc[i][j][3];
            if (EPI == 1) {
                float b0 = bias[mr], b1 = bias[mr + 8];
                v0 += b0; v1 += b0; v2 += b1; v3 += b1;
                if (mr < relu_limit)     { v0 = fmaxf(v0, 0.f); v1 = fmaxf(v1, 0.f); }
                if (mr + 8 < relu_limit) { v2 = fmaxf(v2, 0.f); v3 = fmaxf(v3, 0.f); }
            } else if (EPI == 3) {
                const float* ax = aux + (long)bz * aux_bs;
                float b0 = bias[mr], b1 = bias[mr + 8];
                const float2 r0 = *reinterpret_cast<const float2*>(ax + (long)mr * ldc + nc);
                const float2 r1 = *reinterpret_cast<const float2*>(ax + (long)(mr + 8) * ldc + nc);
                v0 += b0 + r0.x; v1 += b0 + r0.y;
                v2 += b1 + r1.x; v3 += b1 + r1.y;
            }
            if (OUT == 0) {
                float* Cb = C + (long)bz * c_bs;
                float2 s0; s0.x = v0; s0.y = v1;
                float2 s1; s1.x = v2; s1.y = v3;
                *reinterpret_cast<float2*>(Cb + (long)mr * ldc + nc)       = s0;
                *reinterpret_cast<float2*>(Cb + (long)(mr + 8) * ldc + nc) = s1;
            } else if (OUT == 1) {
                if (mr < MID) {                               // f -> GEMM2 A-pack
                    __half* base = o0 + (size_t)bz * NN * MID;
                    base[addrA_h(nc,     mr,     16)] = __float2half_rn(v0);
                    base[addrA_h(nc + 1, mr,     16)] = __float2half_rn(v1);
                    base[addrA_h(nc,     mr + 8, 16)] = __float2half_rn(v2);
                    base[addrA_h(nc + 1, mr + 8, 16)] = __float2half_rn(v3);
                } else if (mr < 2 * MID) {                    // g -> GEMM2 B-pack
                    __half* base = o1 + (size_t)bz * NN * MID;
                    int k = mr - MID;
                    base[addrB_h(k,     nc,     16)] = __float2half_rn(v0);
                    base[addrB_h(k,     nc + 1, 16)] = __float2half_rn(v1);
                    base[addrB_h(k + 8, nc,     16)] = __float2half_rn(v2);
                    base[addrB_h(k + 8, nc + 1, 16)] = __float2half_rn(v3);
                } else {                                      // h -> GEMM4 A-pack
                    __half* base = o2 + (size_t)bz * MID * NN;
                    int m = mr - 2 * MID;
                    // nc even: (v0,v1) and (v2,v3) are adjacent k halves
                    *reinterpret_cast<__half2*>(base + addrA_h(m,     nc, 72)) =
                        __floats2half2_rn(v0, v1);
                    *reinterpret_cast<__half2*>(base + addrA_h(m + 8, nc, 72)) =
                        __floats2half2_rn(v2, v3);
                }
            } else {                                          // OUT==2: z -> GEMM5 B-pack
                __half* base = o0 + (size_t)bz * MID * NN;
                base[addrB_h(mr,     nc,     16)] = __float2half_rn(v0);
                base[addrB_h(mr,     nc + 1, 16)] = __float2half_rn(v1);
                base[addrB_h(mr + 8, nc,     16)] = __float2half_rn(v2);
                base[addrB_h(mr + 8, nc + 1, 16)] = __float2half_rn(v3);
            }
        }
    }
}

// ---------------- row softmax: canonical fp32 in-place + packed fp16 copy -------
__global__ void __launch_bounds__(256)
softmax_kernel(float* __restrict__ attn, __half* __restrict__ apk)
{
    const int row = blockIdx.x;
    const int b = row / NN, nr = row % NN;
    float* p = attn + (size_t)row * NN;
    __half* pk = apk + (size_t)b * NN * NN;
    const int t = threadIdx.x;
    float v[9];
    float mx = -1e30f;
#pragma unroll
    for (int i = 0; i < 9; i++) {
        v[i] = p[t + i * 256];
        mx = fmaxf(mx, v[i]);
    }
    __shared__ float red[8];
#pragma unroll
    for (int o = 16; o > 0; o >>= 1) mx = fmaxf(mx, __shfl_xor_sync(0xffffffffu, mx, o));
    if ((t & 31) == 0) red[t >> 5] = mx;
    __syncthreads();
    if (t == 0) {
        float m = red[0];
#pragma unroll
        for (int i = 1; i < 8; i++) m = fmaxf(m, red[i]);
        red[0] = m;
    }
    __syncthreads();
    mx = red[0];

    float s = 0.f;
#pragma unroll
    for (int i = 0; i < 9; i++) {
        v[i] = expf(v[i] - mx);
        s += v[i];
    }
#pragma unroll
    for (int o = 16; o > 0; o >>= 1) s += __shfl_xor_sync(0xffffffffu, s, o);
    __syncthreads();
    if ((t & 31) == 0) red[t >> 5] = s;
    __syncthreads();
    if (t == 0) {
        float m = 0.f;
#pragma unroll
        for (int i = 0; i < 8; i++) m += red[i];
        red[0] = m;
    }
    __syncthreads();
    float inv = 1.f / red[0];
#pragma unroll
    for (int i = 0; i < 9; i++) {
        float o = v[i] * inv;
        p[t + i * 256] = o;                              // canonical fp32 output
        pk[addrB_h(t + i * 256, nr, 72)] = __float2half_rn(o);   // GEMM4 B operand
    }
}

// ---------------- launch ---------------------------------------------------------
extern "C" void kernel_launch(void* const* d_in, const int* in_sizes, int n_in,
                              void* d_out, int out_size)
{
    const float* x    = (const float*)d_in[0];
    const float* f_w  = (const float*)d_in[1];
    const float* f_b  = (const float*)d_in[2];
    const float* f_g  = (const float*)d_in[3];
    const float* f_be = (const float*)d_in[4];
    const float* f_m  = (const float*)d_in[5];
    const float* f_v  = (const float*)d_in[6];
    const float* g_w  = (const float*)d_in[7];
    const float* g_b  = (const float*)d_in[8];
    const float* g_g  = (const float*)d_in[9];
    const float* g_be = (const float*)d_in[10];
    const float* g_m  = (const float*)d_in[11];
    const float* g_v  = (const float*)d_in[12];
    const float* h_w  = (const float*)d_in[13];
    const float* h_b  = (const float*)d_in[14];
    const float* v_w  = (const float*)d_in[15];
    const float* v_b  = (const float*)d_in[16];

    float* out  = (float*)d_out;
    float* attn = out + (size_t)NB * CC * NN;

    __half *wpk, *vpk, *xpk, *fA, *gB, *hA, *aB, *zB;
    float *bfold;
    cudaGetSymbolAddress((void**)&wpk,   g_wpk);
    cudaGetSymbolAddress((void**)&bfold, g_bfold);
    cudaGetSymbolAddress((void**)&vpk,   g_vpk);
    cudaGetSymbolAddress((void**)&xpk,   g_xpk);
    cudaGetSymbolAddress((void**)&fA,    g_fA);
    cudaGetSymbolAddress((void**)&gB,    g_gB);
    cudaGetSymbolAddress((void**)&hA,    g_hA);
    cudaGetSymbolAddress((void**)&aB,    g_aB);
    cudaGetSymbolAddress((void**)&zB,    g_zB);

    cudaFuncSetAttribute(gemm_h<1, 1>, cudaFuncAttributeMaxDynamicSharedMemorySize, GEMM_SMEM);
    cudaFuncSetAttribute(gemm_h<0, 0>, cudaFuncAttributeMaxDynamicSharedMemorySize, GEMM_SMEM);
    cudaFuncSetAttribute(gemm_h<0, 2>, cudaFuncAttributeMaxDynamicSharedMemorySize, GEMM_SMEM);
    cudaFuncSetAttribute(gemm_h<3, 0>, cudaFuncAttributeMaxDynamicSharedMemorySize, GEMM_SMEM);

    // 0) prep
    prep_bias<<<(M1 + 255) / 256, 256>>>(f_b, f_g, f_be, f_m, f_v,
                                         g_b, g_g, g_be, g_m, g_v, h_b);
    packw_kernel<<<(M1 * CC / 8 + 255) / 256, 256>>>(f_w, f_g, f_v, g_w, g_g, g_v, h_w);
    packv_kernel<<<(CC * MID / 8 + 255) / 256, 256>>>(v_w);
    packx_kernel<<<(NB * NN * CC / 4) / 256, 256>>>(x);

    // 1) FGH = Wfold @ X -> f/g/h consumer-packed (bias + relu rows<1024)
    gemm_h<1, 1><<<dim3(NN / 256, M1 / 128, NB), 256, GEMM_SMEM>>>(
        wpk, 0L, xpk, (long)NN * CC,
        nullptr, 0L, NN, CC, bfold, 2 * MID, nullptr, 0L,
        fA, gB, hA);

    // 2) scores = f^T @ g -> canonical fp32 logits (scale pre-folded in f)
    gemm_h<0, 0><<<dim3(NN / 256, NN / 128, NB), 256, GEMM_SMEM>>>(
        fA, (long)NN * MID, gB, (long)NN * MID,
        attn, (long)NN * NN, NN, MID, nullptr, 0, nullptr, 0L,
        nullptr, nullptr, nullptr);

    // 3) softmax (canonical fp32 + packed fp16 copy)
    softmax_kernel<<<NB * NN, 256>>>(attn, aB);

    // 4) z = h @ attn^T -> GEMM5 B-pack
    gemm_h<0, 2><<<dim3(NN / 256, MID / 128, NB), 256, GEMM_SMEM>>>(
        hA, (long)MID * NN, aB, (long)NN * NN,
        nullptr, 0L, NN, NN, nullptr, 0, nullptr, 0L,
        zB, nullptr, nullptr);

    // 5) out = v_w @ z + v_b + x
    gemm_h<3, 0><<<dim3(NN / 256, CC / 128, NB), 256, GEMM_SMEM>>>(
        vpk, 0L, zB, (long)MID * NN,
        out, (long)CC * NN, NN, MID, v_b, 0, x, (long)CC * NN,
        nullptr, nullptr, nullptr);
}

// round 10
// speedup vs baseline: 3.3310x; 1.0741x over previous
#include <cuda_runtime.h>
#include <cuda_fp16.h>
#include <cstdint>
#include <cmath>

#define NB   8
#define CC   2048
#define NN   2304
#define MID  512
#define M1   1536

// ---------------- scratch (fp16 packed operands) -------------------------------
__device__ __half g_wpk[(size_t)M1 * CC];        // packed folded weights (GEMM1 A)
__device__ float  g_bfold[M1];
__device__ __half g_vpk[(size_t)CC * MID];       // packed v_w (GEMM5 A)
__device__ __half g_xpk[(size_t)NB * NN * CC];   // packed x (GEMM1 B)
__device__ __half g_fA[(size_t)NB * NN * MID];   // f, GEMM2-A-packed
__device__ __half g_gB[(size_t)NB * NN * MID];   // g, GEMM2-B-packed
__device__ __half g_hA[(size_t)NB * MID * NN];   // h, GEMM4-A-packed
__device__ __half g_aB[(size_t)NB * NN * NN];    // attn, GEMM4-B-packed
__device__ __half g_zB[(size_t)NB * MID * NN];   // z, GEMM5-B-packed

// ---------------- helpers ------------------------------------------------------
__device__ __forceinline__ uint32_t smem_u32(const void* p) {
    uint32_t a;
    asm("{ .reg .u64 t; cvta.to.shared.u64 t, %1; cvt.u32.u64 %0, t; }" : "=r"(a) : "l"(p));
    return a;
}
__device__ __forceinline__ void mma_f16(float* c, const uint32_t* a, const uint32_t* b) {
    asm volatile(
        "mma.sync.aligned.m16n8k16.row.col.f32.f16.f16.f32 "
        "{%0,%1,%2,%3}, {%4,%5,%6,%7}, {%8,%9}, {%0,%1,%2,%3};\n"
        : "+f"(c[0]), "+f"(c[1]), "+f"(c[2]), "+f"(c[3])
        : "r"(a[0]), "r"(a[1]), "r"(a[2]), "r"(a[3]), "r"(b[0]), "r"(b[1]));
}
__device__ __forceinline__ void cp16(uint32_t saddr, const void* gaddr) {
    asm volatile("cp.async.cg.shared.global [%0], [%1], 16;" :: "r"(saddr), "l"(gaddr) : "memory");
}

// A-pack (halves): slab(mblk*KT32+kt32) = [ks2(2)][mt(8)][lane(32)] uint4 (8 halves)
__device__ __forceinline__ long addrA_h(int m, int k, int KT32) {
    int slab = (m >> 7) * KT32 + (k >> 5);
    int ks2  = (k >> 4) & 1;
    int mt = (m >> 4) & 7, gid = m & 7, rh = (m >> 3) & 1;
    int kk = k & 15, tg = (kk >> 1) & 3, hb = kk & 1, kh = (kk >> 3) & 1;
    int lane = gid * 4 + tg, u = rh + 2 * kh;
    return (long)slab * 4096 + ks2 * 2048 + mt * 256 + lane * 8 + u * 2 + hb;
}
// B-pack (halves): slab(nblk*KT32+kt32) = [ks2(2)][nt(32)][lane(32)] uint2 (4 halves)
__device__ __forceinline__ long addrB_h(int k, int n, int KT32) {
    int slab = (n >> 8) * KT32 + (k >> 5);
    int ks2  = (k >> 4) & 1;
    int nt = (n >> 3) & 31, gid = n & 7;
    int kk = k & 15, tg = (kk >> 1) & 3, hb = kk & 1, u = (kk >> 3) & 1;
    int lane = gid * 4 + tg;
    return (long)slab * 8192 + ks2 * 4096 + nt * 128 + lane * 4 + u * 2 + hb;
}

// ---------------- prep kernels -------------------------------------------------
__global__ void prep_bias(
    const float* __restrict__ f_b, const float* __restrict__ f_g,
    const float* __restrict__ f_be, const float* __restrict__ f_m,
    const float* __restrict__ f_v,
    const float* __restrict__ g_b, const float* __restrict__ g_g,
    const float* __restrict__ g_be, const float* __restrict__ g_m,
    const float* __restrict__ g_v,
    const float* __restrict__ h_b)
{
    const float SC = 0.044194173824159223f;
    int r = blockIdx.x * 256 + threadIdx.x;
    if (r >= M1) return;
    float b;
    if (r < MID) {
        float inv = f_g[r] / sqrtf(f_v[r] + 1e-5f);
        b = (f_b[r] * inv + f_be[r] - f_m[r] * inv) * SC;
    } else if (r < 2 * MID) {
        int rr = r - MID;
        float inv = g_g[rr] / sqrtf(g_v[rr] + 1e-5f);
        b = g_b[rr] * inv + g_be[rr] - g_m[rr] * inv;
    } else {
        b = h_b[r - 2 * MID];
    }
    g_bfold[r] = b;
}

__global__ void packw_kernel(
    const float* __restrict__ f_w, const float* __restrict__ f_g, const float* __restrict__ f_v,
    const float* __restrict__ g_w, const float* __restrict__ g_g, const float* __restrict__ g_v,
    const float* __restrict__ h_w)
{
    const float SC = 0.044194173824159223f;
    int idx = blockIdx.x * 256 + threadIdx.x;     // total M1*CC/8 = 393216
    if (idx >= M1 * CC / 8) return;
    int lane = idx & 31, mt = (idx >> 5) & 7, ks2 = (idx >> 8) & 1;
    int kt = (idx >> 9) & 63, mblk = idx >> 15;
    int gid = lane >> 2, tg = lane & 3;
    __half h8[8];
#pragma unroll
    for (int u = 0; u < 4; u++)
#pragma unroll
        for (int hb = 0; hb < 2; hb++) {
            int m = mblk * 128 + mt * 16 + gid + (u & 1) * 8;
            int k = kt * 32 + ks2 * 16 + (u >> 1) * 8 + tg * 2 + hb;
            float w;
            if (m < MID) {
                float inv = f_g[m] / sqrtf(f_v[m] + 1e-5f);
                w = f_w[m * CC + k] * inv * SC;
            } else if (m < 2 * MID) {
                int rr = m - MID;
                float inv = g_g[rr] / sqrtf(g_v[rr] + 1e-5f);
                w = g_w[rr * CC + k] * inv;
            } else {
                w = h_w[(m - 2 * MID) * CC + k];
            }
            h8[u * 2 + hb] = __float2half_rn(w);
        }
    reinterpret_cast<uint4*>(g_wpk)[idx] = *reinterpret_cast<uint4*>(h8);
}

__global__ void packv_kernel(const float* __restrict__ v_w)
{
    int idx = blockIdx.x * 256 + threadIdx.x;     // total CC*MID/8 = 131072
    if (idx >= CC * MID / 8) return;
    int lane = idx & 31, mt = (idx >> 5) & 7, ks2 = (idx >> 8) & 1;
    int kt = (idx >> 9) & 15, mblk = idx >> 13;
    int gid = lane >> 2, tg = lane & 3;
    __half h8[8];
#pragma unroll
    for (int u = 0; u < 4; u++)
#pragma unroll
        for (int hb = 0; hb < 2; hb++) {
            int m = mblk * 128 + mt * 16 + gid + (u & 1) * 8;
            int k = kt * 32 + ks2 * 16 + (u >> 1) * 8 + tg * 2 + hb;
            h8[u * 2 + hb] = __float2half_rn(v_w[m * MID + k]);
        }
    reinterpret_cast<uint4*>(g_vpk)[idx] = *reinterpret_cast<uint4*>(h8);
}

__global__ void packx_kernel(const float* __restrict__ x)
{
    int idx = blockIdx.x * 256 + threadIdx.x;     // total NB*NN*CC/4 = 9437184
    int lane = idx & 31, nt = (idx >> 5) & 31, ks2 = (idx >> 10) & 1;
    int kt = (idx >> 11) & 63;
    int t = idx >> 17;                            // 0..71
    int nblk = t % 9, b = t / 9;
    int gid = lane >> 2, tg = lane & 3;
    const float* xb = x + (size_t)b * CC * NN;
    int n = nblk * 256 + nt * 8 + gid;
    __half h4[4];
#pragma unroll
    for (int u = 0; u < 2; u++)
#pragma unroll
        for (int hb = 0; hb < 2; hb++) {
            int k = kt * 32 + ks2 * 16 + u * 8 + tg * 2 + hb;
            h4[u * 2 + hb] = __float2half_rn(xb[(size_t)k * NN + n]);
        }
    reinterpret_cast<uint2*>(g_xpk)[idx] = *reinterpret_cast<uint2*>(h4);
}

// ---------------- packed fp16 GEMM, 128x256 CTA tile, 64-K stages ---------------
// C[m][n] = sum_k A(m,k)*B(k,n); operands fragment-packed fp16 (32-k slabs,
// two consecutive slabs loaded per stage), fp32 accum.
constexpr int ST = 4;
constexpr int A_HALF = 8192;                     // 128 x 64k halves (2 slabs)
constexpr int B_HALF = 16384;                    // 256 x 64k halves (2 slabs)
constexpr int STAGE_HALF = A_HALF + B_HALF;      // 24576 halves = 48KB
constexpr int GEMM_SMEM = ST * STAGE_HALF * 2;   // 196608 B

template <int EPI, int OUT>
__global__ void __launch_bounds__(256, 1)
gemm_h(const __half* __restrict__ A, long a_bs,
       const __half* __restrict__ B, long b_bs,
       float* __restrict__ C, long c_bs, int ldc,
       int K,
       const float* __restrict__ bias, int relu_limit,
       const float* __restrict__ aux, long aux_bs,
       __half* __restrict__ o0, __half* __restrict__ o1, __half* __restrict__ o2)
{
    extern __shared__ __half sm[];
    const uint32_t sm_base = smem_u32(sm);

    const int tid  = threadIdx.x;
    const int lane = tid & 31;
    const int wid  = tid >> 5;
    const int gid  = lane >> 2;
    const int tg   = lane & 3;
    const int wm   = (wid & 1) * 64;
    const int wn   = (wid >> 1) * 64;
    const int m0   = blockIdx.y * 128;
    const int n0   = blockIdx.x * 256;
    const int bz   = blockIdx.z;

    A += (long)bz * a_bs;
    B += (long)bz * b_bs;

    const int KT32 = K / 32;
    const int KT64 = K / 64;

    float acc[4][8][4];
#pragma unroll
    for (int i = 0; i < 4; i++)
#pragma unroll
        for (int j = 0; j < 8; j++)
#pragma unroll
            for (int r = 0; r < 4; r++) acc[i][j][r] = 0.0f;

    auto load_stage = [&](int s, int kt64) {
        const uint32_t sa = sm_base + s * STAGE_HALF * 2;
        const uint32_t sb = sa + A_HALF * 2;
        const __half* ga = A + ((long)blockIdx.y * KT32 + kt64 * 2) * 4096;
#pragma unroll
        for (int i = 0; i < 4; i++) {
            int idx = tid + i * 256;
            cp16(sa + idx * 16, ga + idx * 8);
        }
        const __half* gb = B + ((long)blockIdx.x * KT32 + kt64 * 2) * 8192;
#pragma unroll
        for (int i = 0; i < 8; i++) {
            int idx = tid + i * 256;
            cp16(sb + idx * 16, gb + idx * 8);
        }
    };

#pragma unroll
    for (int kt = 0; kt < ST - 1; kt++) {
        if (kt < KT64) load_stage(kt, kt);
        asm volatile("cp.async.commit_group;" ::: "memory");
    }

    for (int kt = 0; kt < KT64; kt++) {
        const int s = kt % ST;
        asm volatile("cp.async.wait_group %0;" :: "n"(ST - 2) : "memory");
        __syncthreads();

        const int ktl = kt + ST - 1;
        if (ktl < KT64) load_stage(ktl % ST, ktl);
        asm volatile("cp.async.commit_group;" ::: "memory");

        const __half* as = sm + s * STAGE_HALF;
        const __half* bs = as + A_HALF;
#pragma unroll
        for (int ksl = 0; ksl < 2; ksl++) {         // two 32-k slabs per stage
            const uint4* A4 = reinterpret_cast<const uint4*>(as + ksl * 4096);
            const uint2* B2 = reinterpret_cast<const uint2*>(bs + ksl * 8192);
#pragma unroll
            for (int ks2 = 0; ks2 < 2; ks2++) {
                uint32_t afr[4][4], bfr[8][2];
#pragma unroll
                for (int i = 0; i < 4; i++) {
                    const uint4 av = A4[(ks2 * 8 + (wid & 1) * 4 + i) * 32 + lane];
                    afr[i][0] = av.x; afr[i][1] = av.y;
                    afr[i][2] = av.z; afr[i][3] = av.w;
                }
#pragma unroll
                for (int j = 0; j < 8; j++) {
                    const uint2 bv = B2[(ks2 * 32 + (wid >> 1) * 8 + j) * 32 + lane];
                    bfr[j][0] = bv.x; bfr[j][1] = bv.y;
                }
#pragma unroll
                for (int i = 0; i < 4; i++)
#pragma unroll
                    for (int j = 0; j < 8; j++)
                        mma_f16(acc[i][j], afr[i], bfr[j]);
            }
        }
    }

    // ---------------- epilogue ----------------
#pragma unroll
    for (int i = 0; i < 4; i++) {
        int mr = m0 + wm + i * 16 + gid;
#pragma unroll
        for (int j = 0; j < 8; j++) {
            int nc = n0 + wn + j * 8 + tg * 2;
            float v0 = acc[i][j][0], v1 = acc[i][j][1];
            float v2 = acc[i][j][2], v3 = acc[i][j][3];
            if (EPI == 1) {
                float b0 = bias[mr], b1 = bias[mr + 8];
                v0 += b0; v1 += b0; v2 += b1; v3 += b1;
                if (mr < relu_limit)     { v0 = fmaxf(v0, 0.f); v1 = fmaxf(v1, 0.f); }
                if (mr + 8 < relu_limit) { v2 = fmaxf(v2, 0.f); v3 = fmaxf(v3, 0.f); }
            } else if (EPI == 3) {
                const float* ax = aux + (long)bz * aux_bs;
                float b0 = bias[mr], b1 = bias[mr + 8];
                const float2 r0 = *reinterpret_cast<const float2*>(ax + (long)mr * ldc + nc);
                const float2 r1 = *reinterpret_cast<const float2*>(ax + (long)(mr + 8) * ldc + nc);
                v0 += b0 + r0.x; v1 += b0 + r0.y;
                v2 += b1 + r1.x; v3 += b1 + r1.y;
            }
            if (OUT == 0) {
                float* Cb = C + (long)bz * c_bs;
                float2 s0; s0.x = v0; s0.y = v1;
                float2 s1; s1.x = v2; s1.y = v3;
                *reinterpret_cast<float2*>(Cb + (long)mr * ldc + nc)       = s0;
                *reinterpret_cast<float2*>(Cb + (long)(mr + 8) * ldc + nc) = s1;
            } else if (OUT == 1) {
                if (mr < MID) {                               // f -> GEMM2 A-pack
                    __half* base = o0 + (size_t)bz * NN * MID;
                    base[addrA_h(nc,     mr,     16)] = __float2half_rn(v0);
                    base[addrA_h(nc + 1, mr,     16)] = __float2half_rn(v1);
                    base[addrA_h(nc,     mr + 8, 16)] = __float2half_rn(v2);
                    base[addrA_h(nc + 1, mr + 8, 16)] = __float2half_rn(v3);
                } else if (mr < 2 * MID) {                    // g -> GEMM2 B-pack
                    __half* base = o1 + (size_t)bz * NN * MID;
                    int k = mr - MID;
                    base[addrB_h(k,     nc,     16)] = __float2half_rn(v0);
                    base[addrB_h(k,     nc + 1, 16)] = __float2half_rn(v1);
                    base[addrB_h(k + 8, nc,     16)] = __float2half_rn(v2);
                    base[addrB_h(k + 8, nc + 1, 16)] = __float2half_rn(v3);
                } else {                                      // h -> GEMM4 A-pack
                    __half* base = o2 + (size_t)bz * MID * NN;
                    int m = mr - 2 * MID;
                    *reinterpret_cast<__half2*>(base + addrA_h(m,     nc, 72)) =
                        __floats2half2_rn(v0, v1);
                    *reinterpret_cast<__half2*>(base + addrA_h(m + 8, nc, 72)) =
                        __floats2half2_rn(v2, v3);
                }
            } else {                                          // OUT==2: z -> GEMM5 B-pack
                __half* base = o0 + (size_t)bz * MID * NN;
                base[addrB_h(mr,     nc,     16)] = __float2half_rn(v0);
                base[addrB_h(mr,     nc + 1, 16)] = __float2half_rn(v1);
                base[addrB_h(mr + 8, nc,     16)] = __float2half_rn(v2);
                base[addrB_h(mr + 8, nc + 1, 16)] = __float2half_rn(v3);
            }
        }
    }
}

// ---------------- row softmax: canonical fp32 + half2 packed copy ---------------
__global__ void __launch_bounds__(256)
softmax_kernel(float* __restrict__ attn, __half* __restrict__ apk)
{
    const int row = blockIdx.x;
    const int b = row / NN, nr = row % NN;
    float* p = attn + (size_t)row * NN;
    __half* pk = apk + (size_t)b * NN * NN;
    const int t = threadIdx.x;
    __shared__ float red[8];
    __shared__ float sv[NN];

    float v[9];
    float mx = -1e30f;
#pragma unroll
    for (int i = 0; i < 9; i++) {
        v[i] = p[t + i * 256];
        mx = fmaxf(mx, v[i]);
    }
#pragma unroll
    for (int o = 16; o > 0; o >>= 1) mx = fmaxf(mx, __shfl_xor_sync(0xffffffffu, mx, o));
    if ((t & 31) == 0) red[t >> 5] = mx;
    __syncthreads();
    if (t == 0) {
        float m = red[0];
#pragma unroll
        for (int i = 1; i < 8; i++) m = fmaxf(m, red[i]);
        red[0] = m;
    }
    __syncthreads();
    mx = red[0];

    float s = 0.f;
#pragma unroll
    for (int i = 0; i < 9; i++) {
        v[i] = expf(v[i] - mx);
        s += v[i];
    }
#pragma unroll
    for (int o = 16; o > 0; o >>= 1) s += __shfl_xor_sync(0xffffffffu, s, o);
    __syncthreads();
    if ((t & 31) == 0) red[t >> 5] = s;
    __syncthreads();
    if (t == 0) {
        float m = 0.f;
#pragma unroll
        for (int i = 0; i < 8; i++) m += red[i];
        red[0] = m;
    }
    __syncthreads();
    float inv = 1.f / red[0];
#pragma unroll
    for (int i = 0; i < 9; i++) {
        float o = v[i] * inv;
        p[t + i * 256] = o;          // canonical fp32 output
        sv[t + i * 256] = o;         // stage for packed half2 writes
    }
    __syncthreads();
    // packed fp16 copy: adjacent k-pairs are contiguous (hb bit) -> half2 stores
    for (int pi = t; pi < NN / 2; pi += 256) {
        int k0 = pi * 2;
        __half2 h = __floats2half2_rn(sv[k0], sv[k0 + 1]);
        *reinterpret_cast<__half2*>(pk + addrB_h(k0, nr, 72)) = h;
    }
}

// ---------------- launch ---------------------------------------------------------
extern "C" void kernel_launch(void* const* d_in, const int* in_sizes, int n_in,
                              void* d_out, int out_size)
{
    const float* x    = (const float*)d_in[0];
    const float* f_w  = (const float*)d_in[1];
    const float* f_b  = (const float*)d_in[2];
    const float* f_g  = (const float*)d_in[3];
    const float* f_be = (const float*)d_in[4];
    const float* f_m  = (const float*)d_in[5];
    const float* f_v  = (const float*)d_in[6];
    const float* g_w  = (const float*)d_in[7];
    const float* g_b  = (const float*)d_in[8];
    const float* g_g  = (const float*)d_in[9];
    const float* g_be = (const float*)d_in[10];
    const float* g_m  = (const float*)d_in[11];
    const float* g_v  = (const float*)d_in[12];
    const float* h_w  = (const float*)d_in[13];
    const float* h_b  = (const float*)d_in[14];
    const float* v_w  = (const float*)d_in[15];
    const float* v_b  = (const float*)d_in[16];

    float* out  = (float*)d_out;
    float* attn = out + (size_t)NB * CC * NN;

    __half *wpk, *vpk, *xpk, *fA, *gB, *hA, *aB, *zB;
    float *bfold;
    cudaGetSymbolAddress((void**)&wpk,   g_wpk);
    cudaGetSymbolAddress((void**)&bfold, g_bfold);
    cudaGetSymbolAddress((void**)&vpk,   g_vpk);
    cudaGetSymbolAddress((void**)&xpk,   g_xpk);
    cudaGetSymbolAddress((void**)&fA,    g_fA);
    cudaGetSymbolAddress((void**)&gB,    g_gB);
    cudaGetSymbolAddress((void**)&hA,    g_hA);
    cudaGetSymbolAddress((void**)&aB,    g_aB);
    cudaGetSymbolAddress((void**)&zB,    g_zB);

    cudaFuncSetAttribute(gemm_h<1, 1>, cudaFuncAttributeMaxDynamicSharedMemorySize, GEMM_SMEM);
    cudaFuncSetAttribute(gemm_h<0, 0>, cudaFuncAttributeMaxDynamicSharedMemorySize, GEMM_SMEM);
    cudaFuncSetAttribute(gemm_h<0, 2>, cudaFuncAttributeMaxDynamicSharedMemorySize, GEMM_SMEM);
    cudaFuncSetAttribute(gemm_h<3, 0>, cudaFuncAttributeMaxDynamicSharedMemorySize, GEMM_SMEM);

    // 0) prep
    prep_bias<<<(M1 + 255) / 256, 256>>>(f_b, f_g, f_be, f_m, f_v,
                                         g_b, g_g, g_be, g_m, g_v, h_b);
    packw_kernel<<<(M1 * CC / 8 + 255) / 256, 256>>>(f_w, f_g, f_v, g_w, g_g, g_v, h_w);
    packv_kernel<<<(CC * MID / 8 + 255) / 256, 256>>>(v_w);
    packx_kernel<<<(NB * NN * CC / 4) / 256, 256>>>(x);

    // 1) FGH = Wfold @ X -> f/g/h consumer-packed (bias + relu rows<1024)
    gemm_h<1, 1><<<dim3(NN / 256, M1 / 128, NB), 256, GEMM_SMEM>>>(
        wpk, 0L, xpk, (long)NN * CC,
        nullptr, 0L, NN, CC, bfold, 2 * MID, nullptr, 0L,
        fA, gB, hA);

    // 2) scores = f^T @ g -> canonical fp32 logits (scale pre-folded in f)
    gemm_h<0, 0><<<dim3(NN / 256, NN / 128, NB), 256, GEMM_SMEM>>>(
        fA, (long)NN * MID, gB, (long)NN * MID,
        attn, (long)NN * NN, NN, MID, nullptr, 0, nullptr, 0L,
        nullptr, nullptr, nullptr);

    // 3) softmax (canonical fp32 + packed half2 copy)
    softmax_kernel<<<NB * NN, 256>>>(attn, aB);

    // 4) z = h @ attn^T -> GEMM5 B-pack
    gemm_h<0, 2><<<dim3(NN / 256, MID / 128, NB), 256, GEMM_SMEM>>>(
        hA, (long)MID * NN, aB, (long)NN * NN,
        nullptr, 0L, NN, NN, nullptr, 0, nullptr, 0L,
        zB, nullptr, nullptr);

    // 5) out = v_w @ z + v_b + x
    gemm_h<3, 0><<<dim3(NN / 256, CC / 128, NB), 256, GEMM_SMEM>>>(
        vpk, 0L, zB, (long)MID * NN,
        out, (long)CC * NN, NN, MID, v_b, 0, x, (long)CC * NN,
        nullptr, nullptr, nullptr);
}

// round 11
// speedup vs baseline: 3.5646x; 1.0701x over previous
#include <cuda_runtime.h>
#include <cuda_fp16.h>
#include <cstdint>
#include <cmath>

#define NB   8
#define CC   2048
#define NN   2304
#define MID  512
#define M1   1536

// ---------------- scratch (fp16 packed operands) -------------------------------
__device__ __half g_wpk[(size_t)M1 * CC];        // packed folded weights (GEMM1 A)
__device__ float  g_bfold[M1];
__device__ __half g_vpk[(size_t)CC * MID];       // packed v_w (GEMM5 A)
__device__ __half g_xpk[(size_t)NB * NN * CC];   // packed x (GEMM1 B)
__device__ __half g_fA[(size_t)NB * NN * MID];   // f, GEMM2-A-packed
__device__ __half g_gB[(size_t)NB * NN * MID];   // g, GEMM2-B-packed
__device__ __half g_hA[(size_t)NB * MID * NN];   // h, GEMM4-A-packed
__device__ __half g_aB[(size_t)NB * NN * NN];    // attn, GEMM4-B-packed
__device__ __half g_zB[(size_t)NB * MID * NN];   // z, GEMM5-B-packed

// ---------------- helpers ------------------------------------------------------
__device__ __forceinline__ uint32_t smem_u32(const void* p) {
    uint32_t a;
    asm("{ .reg .u64 t; cvta.to.shared.u64 t, %1; cvt.u32.u64 %0, t; }" : "=r"(a) : "l"(p));
    return a;
}
__device__ __forceinline__ void mma_f16(float* c, const uint32_t* a, const uint32_t* b) {
    asm volatile(
        "mma.sync.aligned.m16n8k16.row.col.f32.f16.f16.f32 "
        "{%0,%1,%2,%3}, {%4,%5,%6,%7}, {%8,%9}, {%0,%1,%2,%3};\n"
        : "+f"(c[0]), "+f"(c[1]), "+f"(c[2]), "+f"(c[3])
        : "r"(a[0]), "r"(a[1]), "r"(a[2]), "r"(a[3]), "r"(b[0]), "r"(b[1]));
}
__device__ __forceinline__ void cp16(uint32_t saddr, const void* gaddr) {
    asm volatile("cp.async.cg.shared.global [%0], [%1], 16;" :: "r"(saddr), "l"(gaddr) : "memory");
}

// A-pack (halves): slab(mblk*KT32+kt32) = [ks2(2)][mt(8)][lane(32)] uint4 (8 halves)
__device__ __forceinline__ long addrA_h(int m, int k, int KT32) {
    int slab = (m >> 7) * KT32 + (k >> 5);
    int ks2  = (k >> 4) & 1;
    int mt = (m >> 4) & 7, gid = m & 7, rh = (m >> 3) & 1;
    int kk = k & 15, tg = (kk >> 1) & 3, hb = kk & 1, kh = (kk >> 3) & 1;
    int lane = gid * 4 + tg, u = rh + 2 * kh;
    return (long)slab * 4096 + ks2 * 2048 + mt * 256 + lane * 8 + u * 2 + hb;
}
// B-pack (halves): slab(nblk*KT32+kt32) = [ks2(2)][nt(32)][lane(32)] uint2 (4 halves)
__device__ __forceinline__ long addrB_h(int k, int n, int KT32) {
    int slab = (n >> 8) * KT32 + (k >> 5);
    int ks2  = (k >> 4) & 1;
    int nt = (n >> 3) & 31, gid = n & 7;
    int kk = k & 15, tg = (kk >> 1) & 3, hb = kk & 1, u = (kk >> 3) & 1;
    int lane = gid * 4 + tg;
    return (long)slab * 8192 + ks2 * 4096 + nt * 128 + lane * 4 + u * 2 + hb;
}

// ---------------- prep kernels -------------------------------------------------
__global__ void prep_bias(
    const float* __restrict__ f_b, const float* __restrict__ f_g,
    const float* __restrict__ f_be, const float* __restrict__ f_m,
    const float* __restrict__ f_v,
    const float* __restrict__ g_b, const float* __restrict__ g_g,
    const float* __restrict__ g_be, const float* __restrict__ g_m,
    const float* __restrict__ g_v,
    const float* __restrict__ h_b)
{
    const float SC = 0.044194173824159223f;
    int r = blockIdx.x * 256 + threadIdx.x;
    if (r >= M1) return;
    float b;
    if (r < MID) {
        float inv = f_g[r] / sqrtf(f_v[r] + 1e-5f);
        b = (f_b[r] * inv + f_be[r] - f_m[r] * inv) * SC;
    } else if (r < 2 * MID) {
        int rr = r - MID;
        float inv = g_g[rr] / sqrtf(g_v[rr] + 1e-5f);
        b = g_b[rr] * inv + g_be[rr] - g_m[rr] * inv;
    } else {
        b = h_b[r - 2 * MID];
    }
    g_bfold[r] = b;
}

__global__ void packw_kernel(
    const float* __restrict__ f_w, const float* __restrict__ f_g, const float* __restrict__ f_v,
    const float* __restrict__ g_w, const float* __restrict__ g_g, const float* __restrict__ g_v,
    const float* __restrict__ h_w)
{
    const float SC = 0.044194173824159223f;
    int idx = blockIdx.x * 256 + threadIdx.x;     // total M1*CC/8 = 393216
    if (idx >= M1 * CC / 8) return;
    int lane = idx & 31, mt = (idx >> 5) & 7, ks2 = (idx >> 8) & 1;
    int kt = (idx >> 9) & 63, mblk = idx >> 15;
    int gid = lane >> 2, tg = lane & 3;
    __half h8[8];
#pragma unroll
    for (int u = 0; u < 4; u++)
#pragma unroll
        for (int hb = 0; hb < 2; hb++) {
            int m = mblk * 128 + mt * 16 + gid + (u & 1) * 8;
            int k = kt * 32 + ks2 * 16 + (u >> 1) * 8 + tg * 2 + hb;
            float w;
            if (m < MID) {
                float inv = f_g[m] / sqrtf(f_v[m] + 1e-5f);
                w = f_w[m * CC + k] * inv * SC;
            } else if (m < 2 * MID) {
                int rr = m - MID;
                float inv = g_g[rr] / sqrtf(g_v[rr] + 1e-5f);
                w = g_w[rr * CC + k] * inv;
            } else {
                w = h_w[(m - 2 * MID) * CC + k];
            }
            h8[u * 2 + hb] = __float2half_rn(w);
        }
    reinterpret_cast<uint4*>(g_wpk)[idx] = *reinterpret_cast<uint4*>(h8);
}

__global__ void packv_kernel(const float* __restrict__ v_w)
{
    int idx = blockIdx.x * 256 + threadIdx.x;     // total CC*MID/8 = 131072
    if (idx >= CC * MID / 8) return;
    int lane = idx & 31, mt = (idx >> 5) & 7, ks2 = (idx >> 8) & 1;
    int kt = (idx >> 9) & 15, mblk = idx >> 13;
    int gid = lane >> 2, tg = lane & 3;
    __half h8[8];
#pragma unroll
    for (int u = 0; u < 4; u++)
#pragma unroll
        for (int hb = 0; hb < 2; hb++) {
            int m = mblk * 128 + mt * 16 + gid + (u & 1) * 8;
            int k = kt * 32 + ks2 * 16 + (u >> 1) * 8 + tg * 2 + hb;
            h8[u * 2 + hb] = __float2half_rn(v_w[m * MID + k]);
        }
    reinterpret_cast<uint4*>(g_vpk)[idx] = *reinterpret_cast<uint4*>(h8);
}

// packx: one block per (b, nblk, kt) 32k x 256n tile; coalesced float4 reads,
// smem transpose staging, coalesced uint2 packed writes.
__global__ void __launch_bounds__(256)
packx_kernel(const float* __restrict__ x)
{
    __shared__ float sv[32][258];
    int blk  = blockIdx.x;                 // b*9*64 + nblk*64 + kt
    int kt   = blk & 63;
    int nblk = (blk >> 6) % 9;
    int b    = blk / (9 * 64);
    const float* xb = x + (size_t)b * CC * NN + (size_t)(kt * 32) * NN + nblk * 256;
    int t  = threadIdx.x;
    int tr = t >> 6, tc = (t & 63) * 4;
#pragma unroll
    for (int p = 0; p < 8; p++) {
        int r = tr + p * 4;
        float4 vv = *reinterpret_cast<const float4*>(xb + (size_t)r * NN + tc);
        sv[r][tc] = vv.x; sv[r][tc + 1] = vv.y;
        sv[r][tc + 2] = vv.z; sv[r][tc + 3] = vv.w;
    }
    __syncthreads();
    uint2* outp = reinterpret_cast<uint2*>(g_xpk)
                + ((size_t)(b * 9 + nblk) * 64 + kt) * 2048;
#pragma unroll
    for (int i = 0; i < 8; i++) {
        int o = t + i * 256;
        int lane = o & 31, nt = (o >> 5) & 31, ks2 = o >> 10;
        int gid = lane >> 2, tg = lane & 3;
        int n = nt * 8 + gid;
        int kb = ks2 * 16 + tg * 2;
        __half h4[4];
        h4[0] = __float2half_rn(sv[kb][n]);
        h4[1] = __float2half_rn(sv[kb + 1][n]);
        h4[2] = __float2half_rn(sv[kb + 8][n]);
        h4[3] = __float2half_rn(sv[kb + 9][n]);
        outp[o] = *reinterpret_cast<uint2*>(h4);
    }
}

// ---------------- packed fp16 GEMM, 128x256 CTA tile, 64-K stages ---------------
constexpr int ST = 4;
constexpr int A_HALF = 8192;
constexpr int B_HALF = 16384;
constexpr int STAGE_HALF = A_HALF + B_HALF;      // 48KB
constexpr int GEMM_SMEM = ST * STAGE_HALF * 2;   // 196608 B

template <int EPI, int OUT>
__global__ void __launch_bounds__(256, 1)
gemm_h(const __half* __restrict__ A, long a_bs,
       const __half* __restrict__ B, long b_bs,
       float* __restrict__ C, long c_bs, int ldc,
       int K,
       const float* __restrict__ bias, int relu_limit,
       const float* __restrict__ aux, long aux_bs,
       __half* __restrict__ o0, __half* __restrict__ o1, __half* __restrict__ o2)
{
    extern __shared__ __half sm[];
    const uint32_t sm_base = smem_u32(sm);

    const int tid  = threadIdx.x;
    const int lane = tid & 31;
    const int wid  = tid >> 5;
    const int gid  = lane >> 2;
    const int tg   = lane & 3;
    const int wm   = (wid & 1) * 64;
    const int wn   = (wid >> 1) * 64;
    const int m0   = blockIdx.y * 128;
    const int n0   = blockIdx.x * 256;
    const int bz   = blockIdx.z;

    A += (long)bz * a_bs;
    B += (long)bz * b_bs;

    const int KT32 = K / 32;
    const int KT64 = K / 64;

    float acc[4][8][4];
#pragma unroll
    for (int i = 0; i < 4; i++)
#pragma unroll
        for (int j = 0; j < 8; j++)
#pragma unroll
            for (int r = 0; r < 4; r++) acc[i][j][r] = 0.0f;

    auto load_stage = [&](int s, int kt64) {
        const uint32_t sa = sm_base + s * STAGE_HALF * 2;
        const uint32_t sb = sa + A_HALF * 2;
        const __half* ga = A + ((long)blockIdx.y * KT32 + kt64 * 2) * 4096;
#pragma unroll
        for (int i = 0; i < 4; i++) {
            int idx = tid + i * 256;
            cp16(sa + idx * 16, ga + idx * 8);
        }
        const __half* gb = B + ((long)blockIdx.x * KT32 + kt64 * 2) * 8192;
#pragma unroll
        for (int i = 0; i < 8; i++) {
            int idx = tid + i * 256;
            cp16(sb + idx * 16, gb + idx * 8);
        }
    };

    auto compute_slab = [&](const __half* as, const __half* bs, int ksl) {
        const uint4* A4 = reinterpret_cast<const uint4*>(as + ksl * 4096);
        const uint2* B2 = reinterpret_cast<const uint2*>(bs + ksl * 8192);
#pragma unroll
        for (int ks2 = 0; ks2 < 2; ks2++) {
            uint32_t afr[4][4], bfr[8][2];
#pragma unroll
            for (int i = 0; i < 4; i++) {
                const uint4 av = A4[(ks2 * 8 + (wid & 1) * 4 + i) * 32 + lane];
                afr[i][0] = av.x; afr[i][1] = av.y;
                afr[i][2] = av.z; afr[i][3] = av.w;
            }
#pragma unroll
            for (int j = 0; j < 8; j++) {
                const uint2 bv = B2[(ks2 * 32 + (wid >> 1) * 8 + j) * 32 + lane];
                bfr[j][0] = bv.x; bfr[j][1] = bv.y;
            }
#pragma unroll
            for (int i = 0; i < 4; i++)
#pragma unroll
                for (int j = 0; j < 8; j++)
                    mma_f16(acc[i][j], afr[i], bfr[j]);
        }
    };

#pragma unroll
    for (int kt = 0; kt < ST - 1; kt++) {
        if (kt < KT64) load_stage(kt, kt);
        asm volatile("cp.async.commit_group;" ::: "memory");
    }

    for (int kt = 0; kt < KT64; kt++) {
        const int s = kt % ST;
        asm volatile("cp.async.wait_group %0;" :: "n"(ST - 2) : "memory");
        __syncthreads();

        const __half* as = sm + s * STAGE_HALF;
        const __half* bs = as + A_HALF;

        compute_slab(as, bs, 0);                 // overlap with async issue below

        const int ktl = kt + ST - 1;
        if (ktl < KT64) load_stage(ktl % ST, ktl);
        asm volatile("cp.async.commit_group;" ::: "memory");

        compute_slab(as, bs, 1);
    }

    // ---------------- epilogue ----------------
#pragma unroll
    for (int i = 0; i < 4; i++) {
        int mr = m0 + wm + i * 16 + gid;
#pragma unroll
        for (int j = 0; j < 8; j++) {
            int nc = n0 + wn + j * 8 + tg * 2;
            float v0 = acc[i][j][0], v1 = acc[i][j][1];
            float v2 = acc[i][j][2], v3 = acc[i][j][3];
            if (EPI == 1) {
                float b0 = bias[mr], b1 = bias[mr + 8];
                v0 += b0; v1 += b0; v2 += b1; v3 += b1;
                if (mr < relu_limit)     { v0 = fmaxf(v0, 0.f); v1 = fmaxf(v1, 0.f); }
                if (mr + 8 < relu_limit) { v2 = fmaxf(v2, 0.f); v3 = fmaxf(v3, 0.f); }
            } else if (EPI == 3) {
                const float* ax = aux + (long)bz * aux_bs;
                float b0 = bias[mr], b1 = bias[mr + 8];
                const float2 r0 = *reinterpret_cast<const float2*>(ax + (long)mr * ldc + nc);
                const float2 r1 = *reinterpret_cast<const float2*>(ax + (long)(mr + 8) * ldc + nc);
                v0 += b0 + r0.x; v1 += b0 + r0.y;
                v2 += b1 + r1.x; v3 += b1 + r1.y;
            }
            if (OUT == 0) {
                float* Cb = C + (long)bz * c_bs;
                float2 s0; s0.x = v0; s0.y = v1;
                float2 s1; s1.x = v2; s1.y = v3;
                *reinterpret_cast<float2*>(Cb + (long)mr * ldc + nc)       = s0;
                *reinterpret_cast<float2*>(Cb + (long)(mr + 8) * ldc + nc) = s1;
            } else if (OUT == 1) {
                if (mr < MID) {                               // f -> GEMM2 A-pack
                    __half* base = o0 + (size_t)bz * NN * MID;
                    base[addrA_h(nc,     mr,     16)] = __float2half_rn(v0);
                    base[addrA_h(nc + 1, mr,     16)] = __float2half_rn(v1);
                    base[addrA_h(nc,     mr + 8, 16)] = __float2half_rn(v2);
                    base[addrA_h(nc + 1, mr + 8, 16)] = __float2half_rn(v3);
                } else if (mr < 2 * MID) {                    // g -> GEMM2 B-pack
                    __half* base = o1 + (size_t)bz * NN * MID;
                    int k = mr - MID;
                    base[addrB_h(k,     nc,     16)] = __float2half_rn(v0);
                    base[addrB_h(k,     nc + 1, 16)] = __float2half_rn(v1);
                    base[addrB_h(k + 8, nc,     16)] = __float2half_rn(v2);
                    base[addrB_h(k + 8, nc + 1, 16)] = __float2half_rn(v3);
                } else {                                      // h -> GEMM4 A-pack
                    __half* base = o2 + (size_t)bz * MID * NN;
                    int m = mr - 2 * MID;
                    *reinterpret_cast<__half2*>(base + addrA_h(m,     nc, 72)) =
                        __floats2half2_rn(v0, v1);
                    *reinterpret_cast<__half2*>(base + addrA_h(m + 8, nc, 72)) =
                        __floats2half2_rn(v2, v3);
                }
            } else {                                          // OUT==2: z -> GEMM5 B-pack
                __half* base = o0 + (size_t)bz * MID * NN;
                base[addrB_h(mr,     nc,     16)] = __float2half_rn(v0);
                base[addrB_h(mr,     nc + 1, 16)] = __float2half_rn(v1);
                base[addrB_h(mr + 8, nc,     16)] = __float2half_rn(v2);
                base[addrB_h(mr + 8, nc + 1, 16)] = __float2half_rn(v3);
            }
        }
    }
}

// ---------------- row softmax: canonical fp32 + half2 packed copy ---------------
__global__ void __launch_bounds__(256)
softmax_kernel(float* __restrict__ attn, __half* __restrict__ apk)
{
    const int row = blockIdx.x;
    const int b = row / NN, nr = row % NN;
    float* p = attn + (size_t)row * NN;
    __half* pk = apk + (size_t)b * NN * NN;
    const int t = threadIdx.x;
    __shared__ float red[8];
    __shared__ float sv[NN];

    float v[9];
    float mx = -1e30f;
#pragma unroll
    for (int i = 0; i < 9; i++) {
        v[i] = p[t + i * 256];
        mx = fmaxf(mx, v[i]);
    }
#pragma unroll
    for (int o = 16; o > 0; o >>= 1) mx = fmaxf(mx, __shfl_xor_sync(0xffffffffu, mx, o));
    if ((t & 31) == 0) red[t >> 5] = mx;
    __syncthreads();
    if (t == 0) {
        float m = red[0];
#pragma unroll
        for (int i = 1; i < 8; i++) m = fmaxf(m, red[i]);
        red[0] = m;
    }
    __syncthreads();
    mx = red[0];

    float s = 0.f;
#pragma unroll
    for (int i = 0; i < 9; i++) {
        v[i] = __expf(v[i] - mx);
        s += v[i];
    }
#pragma unroll
    for (int o = 16; o > 0; o >>= 1) s += __shfl_xor_sync(0xffffffffu, s, o);
    __syncthreads();
    if ((t & 31) == 0) red[t >> 5] = s;
    __syncthreads();
    if (t == 0) {
        float m = 0.f;
#pragma unroll
        for (int i = 0; i < 8; i++) m += red[i];
        red[0] = m;
    }
    __syncthreads();
    float inv = 1.f / red[0];
#pragma unroll
    for (int i = 0; i < 9; i++) {
        float o = v[i] * inv;
        p[t + i * 256] = o;          // canonical fp32 output
        sv[t + i * 256] = o;         // stage for packed half2 writes
    }
    __syncthreads();
    for (int pi = t; pi < NN / 2; pi += 256) {
        int k0 = pi * 2;
        __half2 h = __floats2half2_rn(sv[k0], sv[k0 + 1]);
        *reinterpret_cast<__half2*>(pk + addrB_h(k0, nr, 72)) = h;
    }
}

// ---------------- launch ---------------------------------------------------------
extern "C" void kernel_launch(void* const* d_in, const int* in_sizes, int n_in,
                              void* d_out, int out_size)
{
    const float* x    = (const float*)d_in[0];
    const float* f_w  = (const float*)d_in[1];
    const float* f_b  = (const float*)d_in[2];
    const float* f_g  = (const float*)d_in[3];
    const float* f_be = (const float*)d_in[4];
    const float* f_m  = (const float*)d_in[5];
    const float* f_v  = (const float*)d_in[6];
    const float* g_w  = (const float*)d_in[7];
    const float* g_b  = (const float*)d_in[8];
    const float* g_g  = (const float*)d_in[9];
    const float* g_be = (const float*)d_in[10];
    const float* g_m  = (const float*)d_in[11];
    const float* g_v  = (const float*)d_in[12];
    const float* h_w  = (const float*)d_in[13];
    const float* h_b  = (const float*)d_in[14];
    const float* v_w  = (const float*)d_in[15];
    const float* v_b  = (const float*)d_in[16];

    float* out  = (float*)d_out;
    float* attn = out + (size_t)NB * CC * NN;

    __half *wpk, *vpk, *xpk, *fA, *gB, *hA, *aB, *zB;
    float *bfold;
    cudaGetSymbolAddress((void**)&wpk,   g_wpk);
    cudaGetSymbolAddress((void**)&bfold, g_bfold);
    cudaGetSymbolAddress((void**)&vpk,   g_vpk);
    cudaGetSymbolAddress((void**)&xpk,   g_xpk);
    cudaGetSymbolAddress((void**)&fA,    g_fA);
    cudaGetSymbolAddress((void**)&gB,    g_gB);
    cudaGetSymbolAddress((void**)&hA,    g_hA);
    cudaGetSymbolAddress((void**)&aB,    g_aB);
    cudaGetSymbolAddress((void**)&zB,    g_zB);

    cudaFuncSetAttribute(gemm_h<1, 1>, cudaFuncAttributeMaxDynamicSharedMemorySize, GEMM_SMEM);
    cudaFuncSetAttribute(gemm_h<0, 0>, cudaFuncAttributeMaxDynamicSharedMemorySize, GEMM_SMEM);
    cudaFuncSetAttribute(gemm_h<0, 2>, cudaFuncAttributeMaxDynamicSharedMemorySize, GEMM_SMEM);
    cudaFuncSetAttribute(gemm_h<3, 0>, cudaFuncAttributeMaxDynamicSharedMemorySize, GEMM_SMEM);

    // 0) prep
    prep_bias<<<(M1 + 255) / 256, 256>>>(f_b, f_g, f_be, f_m, f_v,
                                         g_b, g_g, g_be, g_m, g_v, h_b);
    packw_kernel<<<(M1 * CC / 8 + 255) / 256, 256>>>(f_w, f_g, f_v, g_w, g_g, g_v, h_w);
    packv_kernel<<<(CC * MID / 8 + 255) / 256, 256>>>(v_w);
    packx_kernel<<<NB * 9 * 64, 256>>>(x);

    // 1) FGH = Wfold @ X -> f/g/h consumer-packed (bias + relu rows<1024)
    gemm_h<1, 1><<<dim3(NN / 256, M1 / 128, NB), 256, GEMM_SMEM>>>(
        wpk, 0L, xpk, (long)NN * CC,
        nullptr, 0L, NN, CC, bfold, 2 * MID, nullptr, 0L,
        fA, gB, hA);

    // 2) scores = f^T @ g -> canonical fp32 logits (scale pre-folded in f)
    gemm_h<0, 0><<<dim3(NN / 256, NN / 128, NB), 256, GEMM_SMEM>>>(
        fA, (long)NN * MID, gB, (long)NN * MID,
        attn, (long)NN * NN, NN, MID, nullptr, 0, nullptr, 0L,
        nullptr, nullptr, nullptr);

    // 3) softmax (canonical fp32 + packed half2 copy)
    softmax_kernel<<<NB * NN, 256>>>(attn, aB);

    // 4) z = h @ attn^T -> GEMM5 B-pack
    gemm_h<0, 2><<<dim3(NN / 256, MID / 128, NB), 256, GEMM_SMEM>>>(
        hA, (long)MID * NN, aB, (long)NN * NN,
        nullptr, 0L, NN, NN, nullptr, 0, nullptr, 0L,
        zB, nullptr, nullptr);

    // 5) out = v_w @ z + v_b + x
    gemm_h<3, 0><<<dim3(NN / 256, CC / 128, NB), 256, GEMM_SMEM>>>(
        vpk, 0L, zB, (long)MID * NN,
        out, (long)CC * NN, NN, MID, v_b, 0, x, (long)CC * NN,
        nullptr, nullptr, nullptr);
}